// round 13
// baseline (speedup 1.0000x reference)
#include <cuda_runtime.h>
#include <cuda_fp16.h>
#include <cstdint>
#include <cstdio>

// ---------------- scratch (static device globals; no allocation) ----------------
__device__ float g_tu[2 * 100000 * 64];
__device__ float g_ti[2 * 100000 * 64];
__device__ float g_t [200000 * 64];
__device__ __half g_s [800000 * 64];         // per-cell s buffers (fp16 intermediate)
__device__ float2 g_wT[5 * 2048];            // packed tf32 T-weight frags
__device__ float2 g_wI[5 * 2048];            // packed tf32 I-weight frags
__device__ float2 g_awf[2048];               // packed tf32 attention w1 frags (u,i)

// ---------------- helpers ----------------
__device__ __forceinline__ void red4(float* p, float a, float b, float c, float d) {
    asm volatile("red.global.add.v4.f32 [%0], {%1, %2, %3, %4};"
                 :: "l"(p), "f"(a), "f"(b), "f"(c), "f"(d) : "memory");
}
__device__ __forceinline__ unsigned int tf32c(float f) {
    unsigned int r;
    asm("cvt.rna.tf32.f32 %0, %1;" : "=r"(r) : "f"(f));
    return r;
}
__device__ __forceinline__ void mma_tf32(float c[4],
                                         unsigned int a0, unsigned int a1,
                                         unsigned int a2, unsigned int a3,
                                         unsigned int b0, unsigned int b1) {
    asm("mma.sync.aligned.m16n8k8.row.col.f32.tf32.tf32.f32 "
        "{%0,%1,%2,%3}, {%4,%5,%6,%7}, {%8,%9}, {%0,%1,%2,%3};"
        : "+f"(c[0]), "+f"(c[1]), "+f"(c[2]), "+f"(c[3])
        : "r"(a0), "r"(a1), "r"(a2), "r"(a3), "r"(b0), "r"(b1));
}
__device__ __forceinline__ void cp16(float* dst_smem, const float* src) {
    unsigned d = (unsigned)__cvta_generic_to_shared(dst_smem);
    asm volatile("cp.async.cg.shared.global [%0], [%1], 16;" :: "r"(d), "l"(src));
}

// ---------------- descriptor tables ----------------
struct GCell {
    const float* xA; const float* xB; int nA; int n;
    const float2* wT; const float2* wI;
    const float* Tb; const float* Ib;
    float* outA; float* outB; __half* s;
};
struct GTab { int off[6]; GCell c[5]; };

struct SCell {
    const int* rows; const int* cols; const float* vals; int nnz;
    const __half* sIn; float* outA; int nA; float* outB;
};
struct STab { int off[6]; SCell c[5]; };

// ---------------- combined weight fragment packer (one launch) ----------------
__global__ __launch_bounds__(256) void pack_all(
    const float* tw0, const float* iw0, const float* tw1, const float* iw1,
    const float* tw2, const float* iw2, const float* tw3, const float* iw3,
    const float* tw4, const float* iw4, float2* wT, float2* wI,
    const float* uw1, const float* iw1a, float2* awf)
{
    int idx = blockIdx.x * 256 + threadIdx.x;
    if (idx < 5 * 2048) {
        int c = idx >> 11;
        int kt = (idx >> 8) & 7;
        int nt = (idx >> 5) & 7;
        int l = idx & 31;
        const float* tw; const float* iw;
        switch (c) {
            case 0: tw = tw0; iw = iw0; break;
            case 1: tw = tw1; iw = iw1; break;
            case 2: tw = tw2; iw = iw2; break;
            case 3: tw = tw3; iw = iw3; break;
            default: tw = tw4; iw = iw4; break;
        }
        int k0 = kt * 8 + (l & 3);
        int n0 = nt * 8 + (l >> 2);
        float2 ot, oi;
        ot.x = __uint_as_float(tf32c(tw[k0 * 64 + n0]));
        ot.y = __uint_as_float(tf32c(tw[(k0 + 4) * 64 + n0]));
        oi.x = __uint_as_float(tf32c(iw[k0 * 64 + n0]));
        oi.y = __uint_as_float(tf32c(iw[(k0 + 4) * 64 + n0]));
        wT[idx] = ot;
        wI[idx] = oi;
    } else if (idx < 5 * 2048 + 2048) {
        int j = idx - 5 * 2048;
        int set = j >> 10;
        int kt = (j >> 7) & 7;
        int nt = (j >> 5) & 3;
        int l = j & 31;
        const float* w = set ? iw1a : uw1;
        int k0 = kt * 8 + (l & 3);
        int n0 = nt * 8 + (l >> 2);
        awf[j] = make_float2(
            __uint_as_float(tf32c(w[k0 * 32 + n0])),
            __uint_as_float(tf32c(w[(k0 + 4) * 32 + n0])));
    }
}

// ---------------- fused dual GEMM: grid-stride, cp.async double-buffered ----------------
__device__ __forceinline__ int cell_of(const GTab& tab, int b) {
    int c = 0;
#pragma unroll
    for (int i = 1; i < 5; ++i) c += (b >= tab.off[i]);
    return c;
}

__device__ __forceinline__ void stage_tile(const GTab& tab, int b, float* buf, int tid) {
    int c = cell_of(tab, b);
    const GCell& cl = tab.c[c];
    int row0 = (b - tab.off[c]) * 64;
#pragma unroll
    for (int k = 0; k < 8; ++k) {
        int j = tid + k * 128;              // 1024 tasks: (row, 16B-seg)
        int r = j >> 4, seg = j & 15;
        int gr = row0 + r;
        const float* src;
        if (gr < cl.n)
            src = (gr < cl.nA) ? (cl.xA + (size_t)gr * 64)
                               : (cl.xB + (size_t)(gr - cl.nA) * 64);
        else
            src = cl.xA;                     // dummy valid address; output guarded
        cp16(buf + r * 68 + seg * 4, src + seg * 4);
    }
}

__device__ void compute_tile(const GTab& tab, int b, const float* sX, int tid) {
    int c = cell_of(tab, b);
    const GCell cl = tab.c[c];
    const int row0 = (b - tab.off[c]) * 64;
    const int n = cl.n;

    const int wid = tid >> 5;
    const int lane = tid & 31;
    const int g = lane >> 2;
    const int t4 = lane & 3;
    const float* xr0 = sX + (wid * 16 + g) * 68;
    const float* xr1 = xr0 + 8 * 68;

    float acc[8][4];
#pragma unroll
    for (int nt = 0; nt < 8; ++nt)
#pragma unroll
        for (int i = 0; i < 4; ++i) acc[nt][i] = 0.f;

    // T phase
#pragma unroll
    for (int kt = 0; kt < 8; ++kt) {
        int c0 = kt * 8 + t4;
        unsigned int a0 = tf32c(xr0[c0]);
        unsigned int a1 = tf32c(xr1[c0]);
        unsigned int a2 = tf32c(xr0[c0 + 4]);
        unsigned int a3 = tf32c(xr1[c0 + 4]);
        const float2* wr = cl.wT + kt * 256 + lane;
#pragma unroll
        for (int nt = 0; nt < 8; ++nt) {
            float2 w = wr[nt * 32];
            mma_tf32(acc[nt], a0, a1, a2, a3,
                     __float_as_uint(w.x), __float_as_uint(w.y));
        }
    }

    const int r0 = row0 + wid * 16 + g;
    const int r1 = r0 + 8;
    float* op0 = nullptr; float* op1 = nullptr;
    if (r0 < n) op0 = (r0 < cl.nA) ? (cl.outA + (size_t)r0 * 64)
                                   : (cl.outB + (size_t)(r0 - cl.nA) * 64);
    if (r1 < n) op1 = (r1 < cl.nA) ? (cl.outA + (size_t)r1 * 64)
                                   : (cl.outB + (size_t)(r1 - cl.nA) * 64);

    // midpoint epilogue: write t = acc + Tb
#pragma unroll
    for (int nt = 0; nt < 8; ++nt) {
        int col = nt * 8 + 2 * t4;
        float tbx = cl.Tb[col], tby = cl.Tb[col + 1];
        if (op0) *reinterpret_cast<float2*>(op0 + col) =
            make_float2(acc[nt][0] + tbx, acc[nt][1] + tby);
        if (op1) *reinterpret_cast<float2*>(op1 + col) =
            make_float2(acc[nt][2] + tbx, acc[nt][3] + tby);
    }

    // Q phase (accumulates on top of T)
#pragma unroll
    for (int kt = 0; kt < 8; ++kt) {
        int c0 = kt * 8 + t4;
        float x0 = xr0[c0], x1 = xr1[c0], x2 = xr0[c0 + 4], x3 = xr1[c0 + 4];
        unsigned int q0 = tf32c(x0 * x0);
        unsigned int q1 = tf32c(x1 * x1);
        unsigned int q2 = tf32c(x2 * x2);
        unsigned int q3 = tf32c(x3 * x3);
        const float2* wr = cl.wI + kt * 256 + lane;
#pragma unroll
        for (int nt = 0; nt < 8; ++nt) {
            float2 w = wr[nt * 32];
            mma_tf32(acc[nt], q0, q1, q2, q3,
                     __float_as_uint(w.x), __float_as_uint(w.y));
        }
    }

    // final epilogue: write s = acc + Tb + Ib  (fp16 storage)
#pragma unroll
    for (int nt = 0; nt < 8; ++nt) {
        int col = nt * 8 + 2 * t4;
        float sbx = cl.Tb[col] + cl.Ib[col];
        float sby = cl.Tb[col + 1] + cl.Ib[col + 1];
        if (r0 < n)
            *reinterpret_cast<__half2*>(cl.s + (size_t)r0 * 64 + col) =
                __floats2half2_rn(acc[nt][0] + sbx, acc[nt][1] + sby);
        if (r1 < n)
            *reinterpret_cast<__half2*>(cl.s + (size_t)r1 * 64 + col) =
                __floats2half2_rn(acc[nt][2] + sbx, acc[nt][3] + sby);
    }
}

__global__ __launch_bounds__(128, 6) void gcn_gemm_all(GTab tab, int total)
{
    __shared__ __align__(16) float sbuf[2][64 * 68];
    const int tid = threadIdx.x;
    const int stride = gridDim.x;
    int t0 = (int)blockIdx.x;
    if (t0 >= total) return;

    stage_tile(tab, t0, sbuf[0], tid);
    asm volatile("cp.async.commit_group;" ::: "memory");

    int cur = 0;
    for (int t = t0; t < total; t += stride) {
        int nxt = t + stride;
        if (nxt < total) {
            stage_tile(tab, nxt, sbuf[1 - cur], tid);
            asm volatile("cp.async.commit_group;" ::: "memory");
            asm volatile("cp.async.wait_group 1;" ::: "memory");
        } else {
            asm volatile("cp.async.wait_group 0;" ::: "memory");
        }
        __syncthreads();
        compute_tile(tab, t, sbuf[cur], tid);
        __syncthreads();
        cur ^= 1;
    }
}

// ---------------- fused edge scatter: fp16 gathers (8B/lane), fp32 red.v4 ----------------
__global__ __launch_bounds__(256) void spmm_all(STab tab)
{
    int b = blockIdx.x;
    int c = 0;
#pragma unroll
    for (int i = 1; i < 5; ++i) c += (b >= tab.off[i]);
    const SCell cl = tab.c[c];
    long long t = (long long)(b - tab.off[c]) * 256 + threadIdx.x;
    int l = (int)(t & 15);
    int e0 = (int)(t >> 4) * 2;
    if (e0 >= cl.nnz) return;

    int r0 = __ldg(cl.rows + e0);
    int c0 = __ldg(cl.cols + e0);
    float v0 = __ldg(cl.vals + e0);
    bool has1 = (e0 + 1) < cl.nnz;
    int r1 = r0, c1 = c0;
    float v1 = 0.f;
    if (has1) {
        r1 = __ldg(cl.rows + e0 + 1);
        c1 = __ldg(cl.cols + e0 + 1);
        v1 = __ldg(cl.vals + e0 + 1);
    }
    // both gathers (8B each) issued before any red -> MLP 2
    uint2 u0 = *reinterpret_cast<const uint2*>(cl.sIn + (size_t)c0 * 64 + l * 4);
    uint2 u1 = *reinterpret_cast<const uint2*>(cl.sIn + (size_t)c1 * 64 + l * 4);

    float2 a0 = __half22float2(*reinterpret_cast<__half2*>(&u0.x));
    float2 b0 = __half22float2(*reinterpret_cast<__half2*>(&u0.y));
    float* p0 = ((r0 < cl.nA) ? (cl.outA + (size_t)r0 * 64)
                              : (cl.outB + (size_t)(r0 - cl.nA) * 64)) + l * 4;
    red4(p0, v0 * a0.x, v0 * a0.y, v0 * b0.x, v0 * b0.y);
    if (has1) {
        float2 a1 = __half22float2(*reinterpret_cast<__half2*>(&u1.x));
        float2 b1 = __half22float2(*reinterpret_cast<__half2*>(&u1.y));
        float* p1 = ((r1 < cl.nA) ? (cl.outA + (size_t)r1 * 64)
                                  : (cl.outB + (size_t)(r1 - cl.nA) * 64)) + l * 4;
        red4(p1, v1 * a1.x, v1 * a1.y, v1 * b1.x, v1 * b1.y);
    }
}

// ---------------- persistent tensor-core attention: 256 thr, 128-node tiles ----------------
#define ATT_ROWS   128
#define ATT_TILE_F (ATT_ROWS * 68)
#define ATT_BUF_F  (3 * ATT_TILE_F)
#define ATT_SMEM_F (2 * ATT_BUF_F + 512)

struct ATab {
    const float* tu; const float* ti; const float* t;
    int U, I, nbU, total;
    const float2* awf;
    const float* ub1; const float* uw2;
    const float* ib1; const float* iw2;
    float* out_u; float* out_i;
};

__device__ __forceinline__ void att_bases(const ATab& a, int tile,
                                          const float** z, int& node0, int& N,
                                          int& isU) {
    isU = (tile < a.nbU);
    node0 = (isU ? tile : (tile - a.nbU)) * ATT_ROWS;
    if (isU) {
        N = a.U; z[0] = a.tu; z[1] = a.tu + (size_t)a.U * 64; z[2] = a.t;
    } else {
        N = a.I; z[0] = a.ti; z[1] = a.ti + (size_t)a.I * 64;
        z[2] = a.t + (size_t)a.U * 64;
    }
}

__device__ __forceinline__ void att_stage(const ATab& a, int tile, float* buf, int tid) {
    const float* z[3]; int node0, N, isU;
    att_bases(a, tile, z, node0, N, isU);
#pragma unroll
    for (int r = 0; r < 3; ++r) {
        const float* zr = z[r];
        float* dst = buf + r * ATT_TILE_F;
#pragma unroll
        for (int k = 0; k < 8; ++k) {
            int i = tid + k * 256;          // 2048 tasks: (row, 16B-seg)
            int row = i >> 4, c4 = i & 15;
            int gr = node0 + row;
            const float* src = (gr < N) ? (zr + (size_t)gr * 64) : zr;
            cp16(dst + row * 68 + c4 * 4, src + c4 * 4);
        }
    }
}

__device__ void att_compute(const ATab& a, int tile, const float* buf, float* wl, int tid) {
    const float* z[3]; int node0, N, isU;
    att_bases(a, tile, z, node0, N, isU);
    const float* b1 = isU ? a.ub1 : a.ib1;
    const float* w2 = isU ? a.uw2 : a.iw2;
    const float2* wf = a.awf + (isU ? 0 : 1024);
    float* out = isU ? a.out_u : a.out_i;

    const int wid = tid >> 5;    // 0..7, rows [wid*16, wid*16+16)
    const int lane = tid & 31;
    const int g = lane >> 2;
    const int t4 = lane & 3;

#pragma unroll
    for (int rel = 0; rel < 3; ++rel) {
        const float* xr0 = buf + rel * ATT_TILE_F + (wid * 16 + g) * 68;
        const float* xr1 = xr0 + 8 * 68;
        float acc[4][4];
#pragma unroll
        for (int nt = 0; nt < 4; ++nt)
#pragma unroll
            for (int i = 0; i < 4; ++i) acc[nt][i] = 0.f;
#pragma unroll
        for (int kt = 0; kt < 8; ++kt) {
            int c0 = kt * 8 + t4;
            unsigned int a0 = tf32c(xr0[c0]);
            unsigned int a1 = tf32c(xr1[c0]);
            unsigned int a2 = tf32c(xr0[c0 + 4]);
            unsigned int a3 = tf32c(xr1[c0 + 4]);
            const float2* wr = wf + kt * 128 + lane;
#pragma unroll
            for (int nt = 0; nt < 4; ++nt) {
                float2 w = wr[nt * 32];
                mma_tf32(acc[nt], a0, a1, a2, a3,
                         __float_as_uint(w.x), __float_as_uint(w.y));
            }
        }
        float s0 = 0.f, s1 = 0.f;
#pragma unroll
        for (int nt = 0; nt < 4; ++nt) {
            int col = nt * 8 + 2 * t4;
            float b1x = b1[col], b1y = b1[col + 1];
            float w2x = w2[col], w2y = w2[col + 1];
            s0 += tanhf(acc[nt][0] + b1x) * w2x + tanhf(acc[nt][1] + b1y) * w2y;
            s1 += tanhf(acc[nt][2] + b1x) * w2x + tanhf(acc[nt][3] + b1y) * w2y;
        }
        s0 += __shfl_xor_sync(0xffffffffu, s0, 1);
        s0 += __shfl_xor_sync(0xffffffffu, s0, 2);
        s1 += __shfl_xor_sync(0xffffffffu, s1, 1);
        s1 += __shfl_xor_sync(0xffffffffu, s1, 2);
        if (t4 == 0) {
            int r0 = wid * 16 + g;
            wl[r0 * 4 + rel] = s0;
            wl[(r0 + 8) * 4 + rel] = s1;
        }
    }
    __syncthreads();

    {
        int row = tid >> 1;          // 0..127
        int gr = node0 + row;
        if (gr < N) {
            float w0 = wl[row * 4 + 0], w1v = wl[row * 4 + 1], w2v = wl[row * 4 + 2];
            float mx = fmaxf(w0, fmaxf(w1v, w2v));
            float e0 = __expf(w0 - mx), e1 = __expf(w1v - mx), e2 = __expf(w2v - mx);
            float inv = 1.0f / (e0 + e1 + e2);
            float beta0 = e0 * inv, beta1 = e1 * inv, beta2 = e2 * inv;
            int hoff = (tid & 1) * 32;
            const float* z0p = buf + 0 * ATT_TILE_F + row * 68 + hoff;
            const float* z1p = buf + 1 * ATT_TILE_F + row * 68 + hoff;
            const float* z2p = buf + 2 * ATT_TILE_F + row * 68 + hoff;
            float* op = out + (size_t)gr * 64 + hoff;
#pragma unroll
            for (int i = 0; i < 8; ++i) {
                float4 A = *reinterpret_cast<const float4*>(z0p + i * 4);
                float4 B = *reinterpret_cast<const float4*>(z1p + i * 4);
                float4 C = *reinterpret_cast<const float4*>(z2p + i * 4);
                float4 o;
                o.x = beta0 * A.x + beta1 * B.x + beta2 * C.x;
                o.y = beta0 * A.y + beta1 * B.y + beta2 * C.y;
                o.z = beta0 * A.z + beta1 * B.z + beta2 * C.z;
                o.w = beta0 * A.w + beta1 * B.w + beta2 * C.w;
                *reinterpret_cast<float4*>(op + i * 4) = o;
            }
        }
    }
}

__global__ __launch_bounds__(256) void rel_att_tc(ATab a)
{
    extern __shared__ __align__(16) float sm[];
    float* buf0 = sm;
    float* buf1 = sm + ATT_BUF_F;
    float* wl   = sm + 2 * ATT_BUF_F;
    const int tid = threadIdx.x;
    const int stride = gridDim.x;
    int t0 = (int)blockIdx.x;
    if (t0 >= a.total) return;

    att_stage(a, t0, buf0, tid);
    asm volatile("cp.async.commit_group;" ::: "memory");

    int cur = 0;
    for (int t = t0; t < a.total; t += stride) {
        int nxt = t + stride;
        if (nxt < a.total) {
            att_stage(a, nxt, cur ? buf0 : buf1, tid);
            asm volatile("cp.async.commit_group;" ::: "memory");
            asm volatile("cp.async.wait_group 1;" ::: "memory");
        } else {
            asm volatile("cp.async.wait_group 0;" ::: "memory");
        }
        __syncthreads();
        att_compute(a, t, cur ? buf1 : buf0, wl, tid);
        __syncthreads();
        cur ^= 1;
    }
}

// ---------------- host launcher (serial, fused launches) ----------------
extern "C" void kernel_launch(void* const* d_in, const int* in_sizes, int n_in,
                              void* d_out, int out_size)
{
    const int*   u2i_idx  = (const int*)  d_in[0];
    const float* u2i_val  = (const float*)d_in[1];
    const int*   u2e_idx  = (const int*)  d_in[2];
    const float* u2e_val  = (const float*)d_in[3];
    const int*   i2e_idx  = (const int*)  d_in[4];
    const float* i2e_val  = (const float*)d_in[5];
    const float* u_feat   = (const float*)d_in[6];
    const float* i_feat   = (const float*)d_in[7];
    const float* u2e_feat = (const float*)d_in[8];
    const float* i2e_feat = (const float*)d_in[9];
    const float* Tw_u2i = (const float*)d_in[10];
    const float* Tb_u2i = (const float*)d_in[11];
    const float* Iw_u2i = (const float*)d_in[12];
    const float* Ib_u2i = (const float*)d_in[13];
    const float* Tw_u2e = (const float*)d_in[14];
    const float* Tb_u2e = (const float*)d_in[15];
    const float* Iw_u2e = (const float*)d_in[16];
    const float* Ib_u2e = (const float*)d_in[17];
    const float* Tw_i2e = (const float*)d_in[18];
    const float* Tb_i2e = (const float*)d_in[19];
    const float* Iw_i2e = (const float*)d_in[20];
    const float* Ib_i2e = (const float*)d_in[21];
    const float* uatt_w1 = (const float*)d_in[22];
    const float* uatt_b1 = (const float*)d_in[23];
    const float* uatt_w2 = (const float*)d_in[24];
    const float* iatt_w1 = (const float*)d_in[25];
    const float* iatt_b1 = (const float*)d_in[26];
    const float* iatt_w2 = (const float*)d_in[27];

    const int U = in_sizes[6] / 64;
    const int I = in_sizes[7] / 64;
    const int E = in_sizes[8] / (2 * 64);
    const int NNZ_UI = in_sizes[1];
    const int NNZ_E  = in_sizes[3] / 2;

    float *tu, *ti, *t;
    __half* s;
    float2 *wT, *wI, *awf;
    cudaGetSymbolAddress((void**)&tu, g_tu);
    cudaGetSymbolAddress((void**)&ti, g_ti);
    cudaGetSymbolAddress((void**)&t,  g_t);
    cudaGetSymbolAddress((void**)&s,  g_s);
    cudaGetSymbolAddress((void**)&wT, g_wT);
    cudaGetSymbolAddress((void**)&wI, g_wI);
    cudaGetSymbolAddress((void**)&awf, g_awf);

    float* outp    = (float*)d_out;
    float* out_u   = outp;
    float* out_i   = outp + (size_t)U * 64;
    float* out_u2e = outp + (size_t)(U + I) * 64;
    float* out_i2e = out_u2e + (size_t)2 * E * 64;

    int ns[5]  = {U + E, U + E, I + E, I + E, U + I};
    int rb[6];
    rb[0] = 0;
    for (int i = 0; i < 5; ++i) rb[i + 1] = rb[i] + ns[i];

    pack_all<<<48, 256>>>(
        Tw_u2e, Iw_u2e, Tw_u2e + 4096, Iw_u2e + 4096,
        Tw_i2e, Iw_i2e, Tw_i2e + 4096, Iw_i2e + 4096,
        Tw_u2i, Iw_u2i, wT, wI,
        uatt_w1, iatt_w1, awf);

    GTab gt;
    {
        const float* xAs[5] = {u_feat, u_feat, i_feat, i_feat, u_feat};
        const float* xBs[5] = {u2e_feat, u2e_feat + (size_t)E * 64,
                               i2e_feat, i2e_feat + (size_t)E * 64, i_feat};
        int gnAs[5] = {U, U, I, I, U};
        const float* Tbs[5] = {Tb_u2e, Tb_u2e + 64, Tb_i2e, Tb_i2e + 64, Tb_u2i};
        const float* Ibs[5] = {Ib_u2e, Ib_u2e + 64, Ib_i2e, Ib_i2e + 64, Ib_u2i};
        float* outAs[5] = {tu, tu + (size_t)U * 64, ti, ti + (size_t)I * 64, t};
        float* outBs[5] = {out_u2e, out_u2e + (size_t)E * 64,
                           out_i2e, out_i2e + (size_t)E * 64, t + (size_t)U * 64};
        gt.off[0] = 0;
        for (int i = 0; i < 5; ++i) {
            gt.c[i].xA = xAs[i]; gt.c[i].xB = xBs[i];
            gt.c[i].nA = gnAs[i]; gt.c[i].n = ns[i];
            gt.c[i].wT = wT + (size_t)i * 2048;
            gt.c[i].wI = wI + (size_t)i * 2048;
            gt.c[i].Tb = Tbs[i]; gt.c[i].Ib = Ibs[i];
            gt.c[i].outA = outAs[i]; gt.c[i].outB = outBs[i];
            gt.c[i].s = s + (size_t)rb[i] * 64;
            gt.off[i + 1] = gt.off[i] + (ns[i] + 63) / 64;
        }
    }
    int totalTiles = gt.off[5];
    int gemmGrid = 152 * 6;
    if (gemmGrid > totalTiles) gemmGrid = totalTiles;
    gcn_gemm_all<<<gemmGrid, 128>>>(gt, totalTiles);

    STab st;
    {
        const int* rws[5] = {u2e_idx, u2e_idx + (size_t)2 * NNZ_E,
                             i2e_idx, i2e_idx + (size_t)2 * NNZ_E, u2i_idx};
        const float* vls[5] = {u2e_val, u2e_val + NNZ_E,
                               i2e_val, i2e_val + NNZ_E, u2i_val};
        int nnzs[5] = {NNZ_E, NNZ_E, NNZ_E, NNZ_E, NNZ_UI};
        int nAs[5]  = {U, U, I, I, U + I};
        float* outAs[5] = {tu, tu + (size_t)U * 64, ti, ti + (size_t)I * 64, t};
        float* outBs[5] = {out_u2e, out_u2e + (size_t)E * 64,
                           out_i2e, out_i2e + (size_t)E * 64, t};
        st.off[0] = 0;
        for (int i = 0; i < 5; ++i) {
            st.c[i].rows = rws[i];
            st.c[i].cols = rws[i] + nnzs[i];
            st.c[i].vals = vls[i];
            st.c[i].nnz = nnzs[i];
            st.c[i].sIn = s + (size_t)rb[i] * 64;
            st.c[i].outA = outAs[i];
            st.c[i].nA = nAs[i];
            st.c[i].outB = outBs[i];
            long long th = ((long long)nnzs[i] + 1) / 2 * 16;
            st.off[i + 1] = st.off[i] + (int)((th + 255) / 256);
        }
    }
    spmm_all<<<st.off[5], 256>>>(st);

    // persistent attention (211KB dynamic smem, 1 CTA/SM, 8 warps)
    ATab at;
    at.tu = tu; at.ti = ti; at.t = t;
    at.U = U; at.I = I;
    at.nbU = (U + ATT_ROWS - 1) / ATT_ROWS;
    at.total = at.nbU + (I + ATT_ROWS - 1) / ATT_ROWS;
    at.awf = awf;
    at.ub1 = uatt_b1; at.uw2 = uatt_w2;
    at.ib1 = iatt_b1; at.iw2 = iatt_w2;
    at.out_u = out_u; at.out_i = out_i;

    const int smemB = ATT_SMEM_F * 4;
    cudaFuncSetAttribute(rel_att_tc, cudaFuncAttributeMaxDynamicSharedMemorySize, smemB);
    int attGrid = 152;
    if (attGrid > at.total) attGrid = at.total;
    rel_att_tc<<<attGrid, 256, smemB>>>(at);
}

// round 14
// speedup vs baseline: 1.1059x; 1.1059x over previous
#include <cuda_runtime.h>
#include <cuda_fp16.h>
#include <cstdint>
#include <cstdio>

// ---------------- scratch (static device globals; no allocation) ----------------
__device__ __half g_tu[2 * 100000 * 64];
__device__ __half g_ti[2 * 100000 * 64];
__device__ __half g_t [200000 * 64];
__device__ __half g_s [800000 * 64];
__device__ float2 g_wT[5 * 2048];
__device__ float2 g_wI[5 * 2048];
__device__ float2 g_awf[2048];

// ---------------- helpers ----------------
__device__ __forceinline__ void red4(float* p, float a, float b, float c, float d) {
    asm volatile("red.global.add.v4.f32 [%0], {%1, %2, %3, %4};"
                 :: "l"(p), "f"(a), "f"(b), "f"(c), "f"(d) : "memory");
}
__device__ __forceinline__ void redh4(__half* p, float a, float b, float c, float d) {
    __half2 h0 = __floats2half2_rn(a, b);
    __half2 h1 = __floats2half2_rn(c, d);
    unsigned x = *reinterpret_cast<unsigned*>(&h0);
    unsigned y = *reinterpret_cast<unsigned*>(&h1);
    asm volatile("red.global.add.noftz.v2.f16x2 [%0], {%1, %2};"
                 :: "l"(p), "r"(x), "r"(y) : "memory");
}
__device__ __forceinline__ unsigned int tf32c(float f) {
    unsigned int r;
    asm("cvt.rna.tf32.f32 %0, %1;" : "=r"(r) : "f"(f));
    return r;
}
__device__ __forceinline__ void mma_tf32(float c[4],
                                         unsigned int a0, unsigned int a1,
                                         unsigned int a2, unsigned int a3,
                                         unsigned int b0, unsigned int b1) {
    asm("mma.sync.aligned.m16n8k8.row.col.f32.tf32.tf32.f32 "
        "{%0,%1,%2,%3}, {%4,%5,%6,%7}, {%8,%9}, {%0,%1,%2,%3};"
        : "+f"(c[0]), "+f"(c[1]), "+f"(c[2]), "+f"(c[3])
        : "r"(a0), "r"(a1), "r"(a2), "r"(a3), "r"(b0), "r"(b1));
}
__device__ __forceinline__ void cp16(void* dst_smem, const void* src) {
    unsigned d = (unsigned)__cvta_generic_to_shared(dst_smem);
    asm volatile("cp.async.cg.shared.global [%0], [%1], 16;" :: "r"(d), "l"(src));
}

// ---------------- descriptor tables ----------------
// nX: x-concat split. nH: rows < nH -> fp16 outA (internal); rows >= nH -> fp32 outB (output).
struct GCell {
    const float* xA; const float* xB; int nX; int nH; int n;
    const float2* wT; const float2* wI;
    const float* Tb; const float* Ib;
    __half* outA; float* outB; __half* s;
};
struct GTab { int off[6]; GCell c[5]; };

struct SCell {
    const int* rows; const int* cols; const float* vals; int nnz;
    const __half* sIn; __half* outA; int nH; float* outB;
};
struct STab { int off[6]; SCell c[5]; };

// ---------------- combined weight fragment packer ----------------
__global__ __launch_bounds__(256) void pack_all(
    const float* tw0, const float* iw0, const float* tw1, const float* iw1,
    const float* tw2, const float* iw2, const float* tw3, const float* iw3,
    const float* tw4, const float* iw4, float2* wT, float2* wI,
    const float* uw1, const float* iw1a, float2* awf)
{
    int idx = blockIdx.x * 256 + threadIdx.x;
    if (idx < 5 * 2048) {
        int c = idx >> 11;
        int kt = (idx >> 8) & 7;
        int nt = (idx >> 5) & 7;
        int l = idx & 31;
        const float* tw; const float* iw;
        switch (c) {
            case 0: tw = tw0; iw = iw0; break;
            case 1: tw = tw1; iw = iw1; break;
            case 2: tw = tw2; iw = iw2; break;
            case 3: tw = tw3; iw = iw3; break;
            default: tw = tw4; iw = iw4; break;
        }
        int k0 = kt * 8 + (l & 3);
        int n0 = nt * 8 + (l >> 2);
        float2 ot, oi;
        ot.x = __uint_as_float(tf32c(tw[k0 * 64 + n0]));
        ot.y = __uint_as_float(tf32c(tw[(k0 + 4) * 64 + n0]));
        oi.x = __uint_as_float(tf32c(iw[k0 * 64 + n0]));
        oi.y = __uint_as_float(tf32c(iw[(k0 + 4) * 64 + n0]));
        wT[idx] = ot;
        wI[idx] = oi;
    } else if (idx < 5 * 2048 + 2048) {
        int j = idx - 5 * 2048;
        int set = j >> 10;
        int kt = (j >> 7) & 7;
        int nt = (j >> 5) & 3;
        int l = j & 31;
        const float* w = set ? iw1a : uw1;
        int k0 = kt * 8 + (l & 3);
        int n0 = nt * 8 + (l >> 2);
        awf[j] = make_float2(
            __uint_as_float(tf32c(w[k0 * 32 + n0])),
            __uint_as_float(tf32c(w[(k0 + 4) * 32 + n0])));
    }
}

// ---------------- fused dual GEMM ----------------
__device__ __forceinline__ int cell_of(const GTab& tab, int b) {
    int c = 0;
#pragma unroll
    for (int i = 1; i < 5; ++i) c += (b >= tab.off[i]);
    return c;
}

__device__ __forceinline__ void stage_tile(const GTab& tab, int b, float* buf, int tid) {
    int c = cell_of(tab, b);
    const GCell& cl = tab.c[c];
    int row0 = (b - tab.off[c]) * 64;
#pragma unroll
    for (int k = 0; k < 8; ++k) {
        int j = tid + k * 128;
        int r = j >> 4, seg = j & 15;
        int gr = row0 + r;
        const float* src;
        if (gr < cl.n)
            src = (gr < cl.nX) ? (cl.xA + (size_t)gr * 64)
                               : (cl.xB + (size_t)(gr - cl.nX) * 64);
        else
            src = cl.xA;
        cp16(buf + r * 68 + seg * 4, src + seg * 4);
    }
}

__device__ void compute_tile(const GTab& tab, int b, const float* sX, int tid) {
    int c = cell_of(tab, b);
    const GCell cl = tab.c[c];
    const int row0 = (b - tab.off[c]) * 64;
    const int n = cl.n;

    const int wid = tid >> 5;
    const int lane = tid & 31;
    const int g = lane >> 2;
    const int t4 = lane & 3;
    const float* xr0 = sX + (wid * 16 + g) * 68;
    const float* xr1 = xr0 + 8 * 68;

    float acc[8][4];
#pragma unroll
    for (int nt = 0; nt < 8; ++nt)
#pragma unroll
        for (int i = 0; i < 4; ++i) acc[nt][i] = 0.f;

#pragma unroll
    for (int kt = 0; kt < 8; ++kt) {
        int c0 = kt * 8 + t4;
        unsigned int a0 = tf32c(xr0[c0]);
        unsigned int a1 = tf32c(xr1[c0]);
        unsigned int a2 = tf32c(xr0[c0 + 4]);
        unsigned int a3 = tf32c(xr1[c0 + 4]);
        const float2* wr = cl.wT + kt * 256 + lane;
#pragma unroll
        for (int nt = 0; nt < 8; ++nt) {
            float2 w = wr[nt * 32];
            mma_tf32(acc[nt], a0, a1, a2, a3,
                     __float_as_uint(w.x), __float_as_uint(w.y));
        }
    }

    const int r0 = row0 + wid * 16 + g;
    const int r1 = r0 + 8;

#pragma unroll
    for (int nt = 0; nt < 8; ++nt) {
        int col = nt * 8 + 2 * t4;
        float tbx = cl.Tb[col], tby = cl.Tb[col + 1];
        if (r0 < n) {
            float tv0 = acc[nt][0] + tbx, tv1 = acc[nt][1] + tby;
            if (r0 < cl.nH)
                *reinterpret_cast<__half2*>(cl.outA + (size_t)r0 * 64 + col) =
                    __floats2half2_rn(tv0, tv1);
            else
                *reinterpret_cast<float2*>(cl.outB + (size_t)(r0 - cl.nH) * 64 + col) =
                    make_float2(tv0, tv1);
        }
        if (r1 < n) {
            float tv0 = acc[nt][2] + tbx, tv1 = acc[nt][3] + tby;
            if (r1 < cl.nH)
                *reinterpret_cast<__half2*>(cl.outA + (size_t)r1 * 64 + col) =
                    __floats2half2_rn(tv0, tv1);
            else
                *reinterpret_cast<float2*>(cl.outB + (size_t)(r1 - cl.nH) * 64 + col) =
                    make_float2(tv0, tv1);
        }
    }

#pragma unroll
    for (int kt = 0; kt < 8; ++kt) {
        int c0 = kt * 8 + t4;
        float x0 = xr0[c0], x1 = xr1[c0], x2 = xr0[c0 + 4], x3 = xr1[c0 + 4];
        unsigned int q0 = tf32c(x0 * x0);
        unsigned int q1 = tf32c(x1 * x1);
        unsigned int q2 = tf32c(x2 * x2);
        unsigned int q3 = tf32c(x3 * x3);
        const float2* wr = cl.wI + kt * 256 + lane;
#pragma unroll
        for (int nt = 0; nt < 8; ++nt) {
            float2 w = wr[nt * 32];
            mma_tf32(acc[nt], q0, q1, q2, q3,
                     __float_as_uint(w.x), __float_as_uint(w.y));
        }
    }

#pragma unroll
    for (int nt = 0; nt < 8; ++nt) {
        int col = nt * 8 + 2 * t4;
        float sbx = cl.Tb[col] + cl.Ib[col];
        float sby = cl.Tb[col + 1] + cl.Ib[col + 1];
        if (r0 < n)
            *reinterpret_cast<__half2*>(cl.s + (size_t)r0 * 64 + col) =
                __floats2half2_rn(acc[nt][0] + sbx, acc[nt][1] + sby);
        if (r1 < n)
            *reinterpret_cast<__half2*>(cl.s + (size_t)r1 * 64 + col) =
                __floats2half2_rn(acc[nt][2] + sbx, acc[nt][3] + sby);
    }
}

__global__ __launch_bounds__(128, 5) void gcn_gemm_all(GTab tab, int total)
{
    __shared__ __align__(16) float sbuf[2][64 * 68];
    const int tid = threadIdx.x;
    const int stride = gridDim.x;
    int t0 = (int)blockIdx.x;
    if (t0 >= total) return;

    stage_tile(tab, t0, sbuf[0], tid);
    asm volatile("cp.async.commit_group;" ::: "memory");

    int cur = 0;
    for (int t = t0; t < total; t += stride) {
        int nxt = t + stride;
        if (nxt < total) {
            stage_tile(tab, nxt, sbuf[1 - cur], tid);
            asm volatile("cp.async.commit_group;" ::: "memory");
            asm volatile("cp.async.wait_group 1;" ::: "memory");
        } else {
            asm volatile("cp.async.wait_group 0;" ::: "memory");
        }
        __syncthreads();
        compute_tile(tab, t, sbuf[cur], tid);
        __syncthreads();
        cur ^= 1;
    }
}

// ---------------- fused edge scatter ----------------
__global__ __launch_bounds__(256) void spmm_all(STab tab)
{
    int b = blockIdx.x;
    int c = 0;
#pragma unroll
    for (int i = 1; i < 5; ++i) c += (b >= tab.off[i]);
    const SCell cl = tab.c[c];
    long long t = (long long)(b - tab.off[c]) * 256 + threadIdx.x;
    int l = (int)(t & 15);
    int e0 = (int)(t >> 4) * 2;
    if (e0 >= cl.nnz) return;

    int r0 = __ldg(cl.rows + e0);
    int c0 = __ldg(cl.cols + e0);
    float v0 = __ldg(cl.vals + e0);
    bool has1 = (e0 + 1) < cl.nnz;
    int r1 = r0, c1 = c0;
    float v1 = 0.f;
    if (has1) {
        r1 = __ldg(cl.rows + e0 + 1);
        c1 = __ldg(cl.cols + e0 + 1);
        v1 = __ldg(cl.vals + e0 + 1);
    }
    uint2 u0 = *reinterpret_cast<const uint2*>(cl.sIn + (size_t)c0 * 64 + l * 4);
    uint2 u1 = *reinterpret_cast<const uint2*>(cl.sIn + (size_t)c1 * 64 + l * 4);

    float2 a0 = __half22float2(*reinterpret_cast<__half2*>(&u0.x));
    float2 b0 = __half22float2(*reinterpret_cast<__half2*>(&u0.y));
    if (r0 < cl.nH)
        redh4(cl.outA + (size_t)r0 * 64 + l * 4,
              v0 * a0.x, v0 * a0.y, v0 * b0.x, v0 * b0.y);
    else
        red4(cl.outB + (size_t)(r0 - cl.nH) * 64 + l * 4,
             v0 * a0.x, v0 * a0.y, v0 * b0.x, v0 * b0.y);
    if (has1) {
        float2 a1 = __half22float2(*reinterpret_cast<__half2*>(&u1.x));
        float2 b1 = __half22float2(*reinterpret_cast<__half2*>(&u1.y));
        if (r1 < cl.nH)
            redh4(cl.outA + (size_t)r1 * 64 + l * 4,
                  v1 * a1.x, v1 * a1.y, v1 * b1.x, v1 * b1.y);
        else
            red4(cl.outB + (size_t)(r1 - cl.nH) * 64 + l * 4,
                 v1 * a1.x, v1 * a1.y, v1 * b1.x, v1 * b1.y);
    }
}

// ---------------- persistent tensor-core attention (fp16 z) ----------------
#define ATT_TILE_H (64 * 72)
#define ATT_BUF_H  (3 * ATT_TILE_H)
#define ATT_SMEM_B (2 * ATT_BUF_H * 2 + 64 * 4 * 4 + 64)

struct ATab {
    const __half* tu; const __half* ti; const __half* t;
    int U, I, nbU, total;
    const float2* awf;
    const float* ub1; const float* uw2;
    const float* ib1; const float* iw2;
    float* out_u; float* out_i;
};

__device__ __forceinline__ void att_bases(const ATab& a, int tile,
                                          const __half** z, int& node0, int& N,
                                          int& isU) {
    isU = (tile < a.nbU);
    node0 = (isU ? tile : (tile - a.nbU)) * 64;
    if (isU) {
        N = a.U; z[0] = a.tu; z[1] = a.tu + (size_t)a.U * 64; z[2] = a.t;
    } else {
        N = a.I; z[0] = a.ti; z[1] = a.ti + (size_t)a.I * 64;
        z[2] = a.t + (size_t)a.U * 64;
    }
}

__device__ __forceinline__ void att_stage(const ATab& a, int tile, __half* buf, int tid) {
    const __half* z[3]; int node0, N, isU;
    att_bases(a, tile, z, node0, N, isU);
#pragma unroll
    for (int r = 0; r < 3; ++r) {
        const __half* zr = z[r];
        __half* dst = buf + r * ATT_TILE_H;
#pragma unroll
        for (int k = 0; k < 4; ++k) {
            int i = tid + k * 128;
            int row = i >> 3, c8 = i & 7;
            int gr = node0 + row;
            const __half* src = (gr < N) ? (zr + (size_t)gr * 64) : zr;
            cp16(dst + row * 72 + c8 * 8, src + c8 * 8);
        }
    }
}

__device__ void att_compute(const ATab& a, int tile, const __half* buf, float* wl, int tid) {
    const __half* z[3]; int node0, N, isU;
    att_bases(a, tile, z, node0, N, isU);
    const float* b1 = isU ? a.ub1 : a.ib1;
    const float* w2 = isU ? a.uw2 : a.iw2;
    const float2* wf = a.awf + (isU ? 0 : 1024);
    float* out = isU ? a.out_u : a.out_i;

    const int wid = tid >> 5;
    const int lane = tid & 31;
    const int g = lane >> 2;
    const int t4 = lane & 3;

#pragma unroll
    for (int rel = 0; rel < 3; ++rel) {
        const __half* xr0 = buf + rel * ATT_TILE_H + (wid * 16 + g) * 72;
        const __half* xr1 = xr0 + 8 * 72;
        float acc[4][4];
#pragma unroll
        for (int nt = 0; nt < 4; ++nt)
#pragma unroll
            for (int i = 0; i < 4; ++i) acc[nt][i] = 0.f;
#pragma unroll
        for (int kt = 0; kt < 8; ++kt) {
            int c0 = kt * 8 + t4;
            unsigned int a0 = tf32c(__half2float(xr0[c0]));
            unsigned int a1 = tf32c(__half2float(xr1[c0]));
            unsigned int a2 = tf32c(__half2float(xr0[c0 + 4]));
            unsigned int a3 = tf32c(__half2float(xr1[c0 + 4]));
            const float2* wr = wf + kt * 128 + lane;
#pragma unroll
            for (int nt = 0; nt < 4; ++nt) {
                float2 w = wr[nt * 32];
                mma_tf32(acc[nt], a0, a1, a2, a3,
                         __float_as_uint(w.x), __float_as_uint(w.y));
            }
        }
        float s0 = 0.f, s1 = 0.f;
#pragma unroll
        for (int nt = 0; nt < 4; ++nt) {
            int col = nt * 8 + 2 * t4;
            float b1x = b1[col], b1y = b1[col + 1];
            float w2x = w2[col], w2y = w2[col + 1];
            s0 += tanhf(acc[nt][0] + b1x) * w2x + tanhf(acc[nt][1] + b1y) * w2y;
            s1 += tanhf(acc[nt][2] + b1x) * w2x + tanhf(acc[nt][3] + b1y) * w2y;
        }
        s0 += __shfl_xor_sync(0xffffffffu, s0, 1);
        s0 += __shfl_xor_sync(0xffffffffu, s0, 2);
        s1 += __shfl_xor_sync(0xffffffffu, s1, 1);
        s1 += __shfl_xor_sync(0xffffffffu, s1, 2);
        if (t4 == 0) {
            int r0 = wid * 16 + g;
            wl[r0 * 4 + rel] = s0;
            wl[(r0 + 8) * 4 + rel] = s1;
        }
    }
    __syncthreads();

    {
        int row = tid >> 1;
        int gr = node0 + row;
        if (gr < N) {
            float w0 = wl[row * 4 + 0], w1v = wl[row * 4 + 1], w2v = wl[row * 4 + 2];
            float mx = fmaxf(w0, fmaxf(w1v, w2v));
            float e0 = __expf(w0 - mx), e1 = __expf(w1v - mx), e2 = __expf(w2v - mx);
            float inv = 1.0f / (e0 + e1 + e2);
            float beta0 = e0 * inv, beta1 = e1 * inv, beta2 = e2 * inv;
            int hoff = (tid & 1) * 32;
            const __half2* z0p = reinterpret_cast<const __half2*>(
                buf + 0 * ATT_TILE_H + row * 72 + hoff);
            const __half2* z1p = reinterpret_cast<const __half2*>(
                buf + 1 * ATT_TILE_H + row * 72 + hoff);
            const __half2* z2p = reinterpret_cast<const __half2*>(
                buf + 2 * ATT_TILE_H + row * 72 + hoff);
            float* op = out + (size_t)gr * 64 + hoff;
#pragma unroll
            for (int i = 0; i < 16; ++i) {
                float2 A = __half22float2(z0p[i]);
                float2 B = __half22float2(z1p[i]);
                float2 C = __half22float2(z2p[i]);
                float2 o;
                o.x = beta0 * A.x + beta1 * B.x + beta2 * C.x;
                o.y = beta0 * A.y + beta1 * B.y + beta2 * C.y;
                *reinterpret_cast<float2*>(op + i * 2) = o;
            }
        }
    }
}

__global__ __launch_bounds__(128) void rel_att_tc(ATab a)
{
    extern __shared__ __align__(16) __half smh[];
    __half* buf0 = smh;
    __half* buf1 = smh + ATT_BUF_H;
    float* wl = reinterpret_cast<float*>(smh + 2 * ATT_BUF_H);
    const int tid = threadIdx.x;
    const int stride = gridDim.x;
    int t0 = (int)blockIdx.x;
    if (t0 >= a.total) return;

    att_stage(a, t0, buf0, tid);
    asm volatile("cp.async.commit_group;" ::: "memory");

    int cur = 0;
    for (int t = t0; t < a.total; t += stride) {
        int nxt = t + stride;
        if (nxt < a.total) {
            att_stage(a, nxt, cur ? buf0 : buf1, tid);
            asm volatile("cp.async.commit_group;" ::: "memory");
            asm volatile("cp.async.wait_group 1;" ::: "memory");
        } else {
            asm volatile("cp.async.wait_group 0;" ::: "memory");
        }
        __syncthreads();
        att_compute(a, t, cur ? buf1 : buf0, wl, tid);
        __syncthreads();
        cur ^= 1;
    }
}

// ---------------- host launcher ----------------
extern "C" void kernel_launch(void* const* d_in, const int* in_sizes, int n_in,
                              void* d_out, int out_size)
{
    const int*   u2i_idx  = (const int*)  d_in[0];
    const float* u2i_val  = (const float*)d_in[1];
    const int*   u2e_idx  = (const int*)  d_in[2];
    const float* u2e_val  = (const float*)d_in[3];
    const int*   i2e_idx  = (const int*)  d_in[4];
    const float* i2e_val  = (const float*)d_in[5];
    const float* u_feat   = (const float*)d_in[6];
    const float* i_feat   = (const float*)d_in[7];
    const float* u2e_feat = (const float*)d_in[8];
    const float* i2e_feat = (const float*)d_in[9];
    const float* Tw_u2i = (const float*)d_in[10];
    const float* Tb_u2i = (const float*)d_in[11];
    const float* Iw_u2i = (const float*)d_in[12];
    const float* Ib_u2i = (const float*)d_in[13];
    const float* Tw_u2e = (const float*)d_in[14];
    const float* Tb_u2e = (const float*)d_in[15];
    const float* Iw_u2e = (const float*)d_in[16];
    const float* Ib_u2e = (const float*)d_in[17];
    const float* Tw_i2e = (const float*)d_in[18];
    const float* Tb_i2e = (const float*)d_in[19];
    const float* Iw_i2e = (const float*)d_in[20];
    const float* Ib_i2e = (const float*)d_in[21];
    const float* uatt_w1 = (const float*)d_in[22];
    const float* uatt_b1 = (const float*)d_in[23];
    const float* uatt_w2 = (const float*)d_in[24];
    const float* iatt_w1 = (const float*)d_in[25];
    const float* iatt_b1 = (const float*)d_in[26];
    const float* iatt_w2 = (const float*)d_in[27];

    const int U = in_sizes[6] / 64;
    const int I = in_sizes[7] / 64;
    const int E = in_sizes[8] / (2 * 64);
    const int NNZ_UI = in_sizes[1];
    const int NNZ_E  = in_sizes[3] / 2;

    __half *tu, *ti, *t, *s;
    float2 *wT, *wI, *awf;
    cudaGetSymbolAddress((void**)&tu, g_tu);
    cudaGetSymbolAddress((void**)&ti, g_ti);
    cudaGetSymbolAddress((void**)&t,  g_t);
    cudaGetSymbolAddress((void**)&s,  g_s);
    cudaGetSymbolAddress((void**)&wT, g_wT);
    cudaGetSymbolAddress((void**)&wI, g_wI);
    cudaGetSymbolAddress((void**)&awf, g_awf);

    float* outp    = (float*)d_out;
    float* out_u   = outp;
    float* out_i   = outp + (size_t)U * 64;
    float* out_u2e = outp + (size_t)(U + I) * 64;
    float* out_i2e = out_u2e + (size_t)2 * E * 64;

    int ns[5]  = {U + E, U + E, I + E, I + E, U + I};
    int rb[6];
    rb[0] = 0;
    for (int i = 0; i < 5; ++i) rb[i + 1] = rb[i] + ns[i];

    pack_all<<<48, 256>>>(
        Tw_u2e, Iw_u2e, Tw_u2e + 4096, Iw_u2e + 4096,
        Tw_i2e, Iw_i2e, Tw_i2e + 4096, Iw_i2e + 4096,
        Tw_u2i, Iw_u2i, wT, wI,
        uatt_w1, iatt_w1, awf);

    GTab gt;
    {
        const float* xAs[5] = {u_feat, u_feat, i_feat, i_feat, u_feat};
        const float* xBs[5] = {u2e_feat, u2e_feat + (size_t)E * 64,
                               i2e_feat, i2e_feat + (size_t)E * 64, i_feat};
        int nXs[5] = {U, U, I, I, U};              // x-concat split
        int nHs[5] = {U, U, I, I, U + I};          // fp16/fp32 output split (cell4 all fp16)
        const float* Tbs[5] = {Tb_u2e, Tb_u2e + 64, Tb_i2e, Tb_i2e + 64, Tb_u2i};
        const float* Ibs[5] = {Ib_u2e, Ib_u2e + 64, Ib_i2e, Ib_i2e + 64, Ib_u2i};
        __half* outAs[5] = {tu, tu + (size_t)U * 64, ti, ti + (size_t)I * 64, t};
        float* outBs[5] = {out_u2e, out_u2e + (size_t)E * 64,
                           out_i2e, out_i2e + (size_t)E * 64, out_u2e};
        gt.off[0] = 0;
        for (int i = 0; i < 5; ++i) {
            gt.c[i].xA = xAs[i]; gt.c[i].xB = xBs[i];
            gt.c[i].nX = nXs[i]; gt.c[i].nH = nHs[i]; gt.c[i].n = ns[i];
            gt.c[i].wT = wT + (size_t)i * 2048;
            gt.c[i].wI = wI + (size_t)i * 2048;
            gt.c[i].Tb = Tbs[i]; gt.c[i].Ib = Ibs[i];
            gt.c[i].outA = outAs[i]; gt.c[i].outB = outBs[i];
            gt.c[i].s = s + (size_t)rb[i] * 64;
            gt.off[i + 1] = gt.off[i] + (ns[i] + 63) / 64;
        }
    }
    int totalTiles = gt.off[5];
    int gemmGrid = 152 * 5;
    if (gemmGrid > totalTiles) gemmGrid = totalTiles;
    gcn_gemm_all<<<gemmGrid, 128>>>(gt, totalTiles);

    STab st;
    {
        const int* rws[5] = {u2e_idx, u2e_idx + (size_t)2 * NNZ_E,
                             i2e_idx, i2e_idx + (size_t)2 * NNZ_E, u2i_idx};
        const float* vls[5] = {u2e_val, u2e_val + NNZ_E,
                               i2e_val, i2e_val + NNZ_E, u2i_val};
        int nnzs[5] = {NNZ_E, NNZ_E, NNZ_E, NNZ_E, NNZ_UI};
        int nHs[5]  = {U, U, I, I, U + I};
        __half* outAs[5] = {tu, tu + (size_t)U * 64, ti, ti + (size_t)I * 64, t};
        float* outBs[5] = {out_u2e, out_u2e + (size_t)E * 64,
                           out_i2e, out_i2e + (size_t)E * 64, out_u2e};
        st.off[0] = 0;
        for (int i = 0; i < 5; ++i) {
            st.c[i].rows = rws[i];
            st.c[i].cols = rws[i] + nnzs[i];
            st.c[i].vals = vls[i];
            st.c[i].nnz = nnzs[i];
            st.c[i].sIn = s + (size_t)rb[i] * 64;
            st.c[i].outA = outAs[i];
            st.c[i].nH = nHs[i];
            st.c[i].outB = outBs[i];
            long long th = ((long long)nnzs[i] + 1) / 2 * 16;
            st.off[i + 1] = st.off[i] + (int)((th + 255) / 256);
        }
    }
    spmm_all<<<st.off[5], 256>>>(st);

    ATab at;
    at.tu = tu; at.ti = ti; at.t = t;
    at.U = U; at.I = I;
    at.nbU = (U + 63) / 64;
    at.total = at.nbU + (I + 63) / 64;
    at.awf = awf;
    at.ub1 = uatt_b1; at.uw2 = uatt_w2;
    at.ib1 = iatt_b1; at.iw2 = iatt_w2;
    at.out_u = out_u; at.out_i = out_i;

    cudaFuncSetAttribute(rel_att_tc, cudaFuncAttributeMaxDynamicSharedMemorySize,
                         ATT_SMEM_B);
    int attGrid = 152 * 4;
    if (attGrid > at.total) attGrid = at.total;
    rel_att_tc<<<attGrid, 128, ATT_SMEM_B>>>(at);
}

// round 15
// speedup vs baseline: 1.1839x; 1.0705x over previous
#include <cuda_runtime.h>
#include <cuda_fp16.h>
#include <cstdint>
#include <cstdio>

// ---------------- scratch (static device globals; no allocation) ----------------
__device__ __half g_tu[2 * 100000 * 64];
__device__ __half g_ti[2 * 100000 * 64];
__device__ __half g_t [200000 * 64];
__device__ __half g_s [800000 * 64];
__device__ float2 g_wT[5 * 2048];
__device__ float2 g_wI[5 * 2048];
__device__ float2 g_awf[2048];

// ---------------- helpers ----------------
__device__ __forceinline__ void red4(float* p, float a, float b, float c, float d) {
    asm volatile("red.global.add.v4.f32 [%0], {%1, %2, %3, %4};"
                 :: "l"(p), "f"(a), "f"(b), "f"(c), "f"(d) : "memory");
}
// fp16 vector red: adds 8 halves (16B) atomically
__device__ __forceinline__ void redh8(__half* p,
                                      float f0, float f1, float f2, float f3,
                                      float f4, float f5, float f6, float f7) {
    __half2 h0 = __floats2half2_rn(f0, f1);
    __half2 h1 = __floats2half2_rn(f2, f3);
    __half2 h2 = __floats2half2_rn(f4, f5);
    __half2 h3 = __floats2half2_rn(f6, f7);
    unsigned x0 = *reinterpret_cast<unsigned*>(&h0);
    unsigned x1 = *reinterpret_cast<unsigned*>(&h1);
    unsigned x2 = *reinterpret_cast<unsigned*>(&h2);
    unsigned x3 = *reinterpret_cast<unsigned*>(&h3);
    asm volatile("red.global.add.noftz.v4.f16x2 [%0], {%1, %2, %3, %4};"
                 :: "l"(p), "r"(x0), "r"(x1), "r"(x2), "r"(x3) : "memory");
}
__device__ __forceinline__ unsigned int tf32c(float f) {
    unsigned int r;
    asm("cvt.rna.tf32.f32 %0, %1;" : "=r"(r) : "f"(f));
    return r;
}
__device__ __forceinline__ void mma_tf32(float c[4],
                                         unsigned int a0, unsigned int a1,
                                         unsigned int a2, unsigned int a3,
                                         unsigned int b0, unsigned int b1) {
    asm("mma.sync.aligned.m16n8k8.row.col.f32.tf32.tf32.f32 "
        "{%0,%1,%2,%3}, {%4,%5,%6,%7}, {%8,%9}, {%0,%1,%2,%3};"
        : "+f"(c[0]), "+f"(c[1]), "+f"(c[2]), "+f"(c[3])
        : "r"(a0), "r"(a1), "r"(a2), "r"(a3), "r"(b0), "r"(b1));
}
__device__ __forceinline__ void cp16(void* dst_smem, const void* src) {
    unsigned d = (unsigned)__cvta_generic_to_shared(dst_smem);
    asm volatile("cp.async.cg.shared.global [%0], [%1], 16;" :: "r"(d), "l"(src));
}

// ---------------- descriptor tables ----------------
struct GCell {
    const float* xA; const float* xB; int nX; int nH; int n;
    const float2* wT; const float2* wI;
    const float* Tb; const float* Ib;
    __half* outA; float* outB; __half* s;
};
struct GTab { int off[6]; GCell c[5]; };

struct SCell {
    const int* rows; const int* cols; const float* vals; int nnz;
    const __half* sIn; __half* outA; int nH; float* outB;
};
struct STab { int off[6]; SCell c[5]; };

// ---------------- combined weight fragment packer ----------------
__global__ __launch_bounds__(256) void pack_all(
    const float* tw0, const float* iw0, const float* tw1, const float* iw1,
    const float* tw2, const float* iw2, const float* tw3, const float* iw3,
    const float* tw4, const float* iw4, float2* wT, float2* wI,
    const float* uw1, const float* iw1a, float2* awf)
{
    int idx = blockIdx.x * 256 + threadIdx.x;
    if (idx < 5 * 2048) {
        int c = idx >> 11;
        int kt = (idx >> 8) & 7;
        int nt = (idx >> 5) & 7;
        int l = idx & 31;
        const float* tw; const float* iw;
        switch (c) {
            case 0: tw = tw0; iw = iw0; break;
            case 1: tw = tw1; iw = iw1; break;
            case 2: tw = tw2; iw = iw2; break;
            case 3: tw = tw3; iw = iw3; break;
            default: tw = tw4; iw = iw4; break;
        }
        int k0 = kt * 8 + (l & 3);
        int n0 = nt * 8 + (l >> 2);
        float2 ot, oi;
        ot.x = __uint_as_float(tf32c(tw[k0 * 64 + n0]));
        ot.y = __uint_as_float(tf32c(tw[(k0 + 4) * 64 + n0]));
        oi.x = __uint_as_float(tf32c(iw[k0 * 64 + n0]));
        oi.y = __uint_as_float(tf32c(iw[(k0 + 4) * 64 + n0]));
        wT[idx] = ot;
        wI[idx] = oi;
    } else if (idx < 5 * 2048 + 2048) {
        int j = idx - 5 * 2048;
        int set = j >> 10;
        int kt = (j >> 7) & 7;
        int nt = (j >> 5) & 3;
        int l = j & 31;
        const float* w = set ? iw1a : uw1;
        int k0 = kt * 8 + (l & 3);
        int n0 = nt * 8 + (l >> 2);
        awf[j] = make_float2(
            __uint_as_float(tf32c(w[k0 * 32 + n0])),
            __uint_as_float(tf32c(w[(k0 + 4) * 32 + n0])));
    }
}

// ---------------- fused dual GEMM ----------------
__device__ __forceinline__ int cell_of(const GTab& tab, int b) {
    int c = 0;
#pragma unroll
    for (int i = 1; i < 5; ++i) c += (b >= tab.off[i]);
    return c;
}

__device__ __forceinline__ void stage_tile(const GTab& tab, int b, float* buf, int tid) {
    int c = cell_of(tab, b);
    const GCell& cl = tab.c[c];
    int row0 = (b - tab.off[c]) * 64;
#pragma unroll
    for (int k = 0; k < 8; ++k) {
        int j = tid + k * 128;
        int r = j >> 4, seg = j & 15;
        int gr = row0 + r;
        const float* src;
        if (gr < cl.n)
            src = (gr < cl.nX) ? (cl.xA + (size_t)gr * 64)
                               : (cl.xB + (size_t)(gr - cl.nX) * 64);
        else
            src = cl.xA;
        cp16(buf + r * 68 + seg * 4, src + seg * 4);
    }
}

__device__ void compute_tile(const GTab& tab, int b, const float* sX, int tid) {
    int c = cell_of(tab, b);
    const GCell cl = tab.c[c];
    const int row0 = (b - tab.off[c]) * 64;
    const int n = cl.n;

    const int wid = tid >> 5;
    const int lane = tid & 31;
    const int g = lane >> 2;
    const int t4 = lane & 3;
    const float* xr0 = sX + (wid * 16 + g) * 68;
    const float* xr1 = xr0 + 8 * 68;

    float acc[8][4];
#pragma unroll
    for (int nt = 0; nt < 8; ++nt)
#pragma unroll
        for (int i = 0; i < 4; ++i) acc[nt][i] = 0.f;

#pragma unroll
    for (int kt = 0; kt < 8; ++kt) {
        int c0 = kt * 8 + t4;
        unsigned int a0 = tf32c(xr0[c0]);
        unsigned int a1 = tf32c(xr1[c0]);
        unsigned int a2 = tf32c(xr0[c0 + 4]);
        unsigned int a3 = tf32c(xr1[c0 + 4]);
        const float2* wr = cl.wT + kt * 256 + lane;
#pragma unroll
        for (int nt = 0; nt < 8; ++nt) {
            float2 w = wr[nt * 32];
            mma_tf32(acc[nt], a0, a1, a2, a3,
                     __float_as_uint(w.x), __float_as_uint(w.y));
        }
    }

    const int r0 = row0 + wid * 16 + g;
    const int r1 = r0 + 8;

#pragma unroll
    for (int nt = 0; nt < 8; ++nt) {
        int col = nt * 8 + 2 * t4;
        float tbx = cl.Tb[col], tby = cl.Tb[col + 1];
        if (r0 < n) {
            float tv0 = acc[nt][0] + tbx, tv1 = acc[nt][1] + tby;
            if (r0 < cl.nH)
                *reinterpret_cast<__half2*>(cl.outA + (size_t)r0 * 64 + col) =
                    __floats2half2_rn(tv0, tv1);
            else
                *reinterpret_cast<float2*>(cl.outB + (size_t)(r0 - cl.nH) * 64 + col) =
                    make_float2(tv0, tv1);
        }
        if (r1 < n) {
            float tv0 = acc[nt][2] + tbx, tv1 = acc[nt][3] + tby;
            if (r1 < cl.nH)
                *reinterpret_cast<__half2*>(cl.outA + (size_t)r1 * 64 + col) =
                    __floats2half2_rn(tv0, tv1);
            else
                *reinterpret_cast<float2*>(cl.outB + (size_t)(r1 - cl.nH) * 64 + col) =
                    make_float2(tv0, tv1);
        }
    }

#pragma unroll
    for (int kt = 0; kt < 8; ++kt) {
        int c0 = kt * 8 + t4;
        float x0 = xr0[c0], x1 = xr1[c0], x2 = xr0[c0 + 4], x3 = xr1[c0 + 4];
        unsigned int q0 = tf32c(x0 * x0);
        unsigned int q1 = tf32c(x1 * x1);
        unsigned int q2 = tf32c(x2 * x2);
        unsigned int q3 = tf32c(x3 * x3);
        const float2* wr = cl.wI + kt * 256 + lane;
#pragma unroll
        for (int nt = 0; nt < 8; ++nt) {
            float2 w = wr[nt * 32];
            mma_tf32(acc[nt], q0, q1, q2, q3,
                     __float_as_uint(w.x), __float_as_uint(w.y));
        }
    }

#pragma unroll
    for (int nt = 0; nt < 8; ++nt) {
        int col = nt * 8 + 2 * t4;
        float sbx = cl.Tb[col] + cl.Ib[col];
        float sby = cl.Tb[col + 1] + cl.Ib[col + 1];
        if (r0 < n)
            *reinterpret_cast<__half2*>(cl.s + (size_t)r0 * 64 + col) =
                __floats2half2_rn(acc[nt][0] + sbx, acc[nt][1] + sby);
        if (r1 < n)
            *reinterpret_cast<__half2*>(cl.s + (size_t)r1 * 64 + col) =
                __floats2half2_rn(acc[nt][2] + sbx, acc[nt][3] + sby);
    }
}

__global__ __launch_bounds__(128, 5) void gcn_gemm_all(GTab tab, int total)
{
    __shared__ __align__(16) float sbuf[2][64 * 68];
    const int tid = threadIdx.x;
    const int stride = gridDim.x;
    int t0 = (int)blockIdx.x;
    if (t0 >= total) return;

    stage_tile(tab, t0, sbuf[0], tid);
    asm volatile("cp.async.commit_group;" ::: "memory");

    int cur = 0;
    for (int t = t0; t < total; t += stride) {
        int nxt = t + stride;
        if (nxt < total) {
            stage_tile(tab, nxt, sbuf[1 - cur], tid);
            asm volatile("cp.async.commit_group;" ::: "memory");
            asm volatile("cp.async.wait_group 1;" ::: "memory");
        } else {
            asm volatile("cp.async.wait_group 0;" ::: "memory");
        }
        __syncthreads();
        compute_tile(tab, t, sbuf[cur], tid);
        __syncthreads();
        cur ^= 1;
    }
}

// ---------------- fused edge scatter: 8 lanes/edge, 16B gathers + 16B reds ----------------
__global__ __launch_bounds__(256) void spmm_all(STab tab)
{
    int b = blockIdx.x;
    int c = 0;
#pragma unroll
    for (int i = 1; i < 5; ++i) c += (b >= tab.off[i]);
    const SCell cl = tab.c[c];
    long long t = (long long)(b - tab.off[c]) * 256 + threadIdx.x;
    int l = (int)(t & 7);            // 8 lanes per edge, lane covers 8 channels (16B)
    int e0 = (int)(t >> 3) * 2;
    if (e0 >= cl.nnz) return;

    int r0 = __ldg(cl.rows + e0);
    int c0 = __ldg(cl.cols + e0);
    float v0 = __ldg(cl.vals + e0);
    bool has1 = (e0 + 1) < cl.nnz;
    int r1 = r0, c1 = c0;
    float v1 = 0.f;
    if (has1) {
        r1 = __ldg(cl.rows + e0 + 1);
        c1 = __ldg(cl.cols + e0 + 1);
        v1 = __ldg(cl.vals + e0 + 1);
    }
    // both gathers (16B each) in flight before any red -> MLP 2
    uint4 u0 = *reinterpret_cast<const uint4*>(cl.sIn + (size_t)c0 * 64 + l * 8);
    uint4 u1 = *reinterpret_cast<const uint4*>(cl.sIn + (size_t)c1 * 64 + l * 8);

    {
        float2 p0 = __half22float2(*reinterpret_cast<__half2*>(&u0.x));
        float2 p1 = __half22float2(*reinterpret_cast<__half2*>(&u0.y));
        float2 p2 = __half22float2(*reinterpret_cast<__half2*>(&u0.z));
        float2 p3 = __half22float2(*reinterpret_cast<__half2*>(&u0.w));
        if (r0 < cl.nH) {
            redh8(cl.outA + (size_t)r0 * 64 + l * 8,
                  v0 * p0.x, v0 * p0.y, v0 * p1.x, v0 * p1.y,
                  v0 * p2.x, v0 * p2.y, v0 * p3.x, v0 * p3.y);
        } else {
            float* p = cl.outB + (size_t)(r0 - cl.nH) * 64 + l * 8;
            red4(p,     v0 * p0.x, v0 * p0.y, v0 * p1.x, v0 * p1.y);
            red4(p + 4, v0 * p2.x, v0 * p2.y, v0 * p3.x, v0 * p3.y);
        }
    }
    if (has1) {
        float2 p0 = __half22float2(*reinterpret_cast<__half2*>(&u1.x));
        float2 p1 = __half22float2(*reinterpret_cast<__half2*>(&u1.y));
        float2 p2 = __half22float2(*reinterpret_cast<__half2*>(&u1.z));
        float2 p3 = __half22float2(*reinterpret_cast<__half2*>(&u1.w));
        if (r1 < cl.nH) {
            redh8(cl.outA + (size_t)r1 * 64 + l * 8,
                  v1 * p0.x, v1 * p0.y, v1 * p1.x, v1 * p1.y,
                  v1 * p2.x, v1 * p2.y, v1 * p3.x, v1 * p3.y);
        } else {
            float* p = cl.outB + (size_t)(r1 - cl.nH) * 64 + l * 8;
            red4(p,     v1 * p0.x, v1 * p0.y, v1 * p1.x, v1 * p1.y);
            red4(p + 4, v1 * p2.x, v1 * p2.y, v1 * p3.x, v1 * p3.y);
        }
    }
}

// ---------------- persistent tensor-core attention (fp16 z) ----------------
#define ATT_TILE_H (64 * 72)
#define ATT_BUF_H  (3 * ATT_TILE_H)
#define ATT_SMEM_B (2 * ATT_BUF_H * 2 + 64 * 4 * 4 + 64)

struct ATab {
    const __half* tu; const __half* ti; const __half* t;
    int U, I, nbU, total;
    const float2* awf;
    const float* ub1; const float* uw2;
    const float* ib1; const float* iw2;
    float* out_u; float* out_i;
};

__device__ __forceinline__ void att_bases(const ATab& a, int tile,
                                          const __half** z, int& node0, int& N,
                                          int& isU) {
    isU = (tile < a.nbU);
    node0 = (isU ? tile : (tile - a.nbU)) * 64;
    if (isU) {
        N = a.U; z[0] = a.tu; z[1] = a.tu + (size_t)a.U * 64; z[2] = a.t;
    } else {
        N = a.I; z[0] = a.ti; z[1] = a.ti + (size_t)a.I * 64;
        z[2] = a.t + (size_t)a.U * 64;
    }
}

__device__ __forceinline__ void att_stage(const ATab& a, int tile, __half* buf, int tid) {
    const __half* z[3]; int node0, N, isU;
    att_bases(a, tile, z, node0, N, isU);
#pragma unroll
    for (int r = 0; r < 3; ++r) {
        const __half* zr = z[r];
        __half* dst = buf + r * ATT_TILE_H;
#pragma unroll
        for (int k = 0; k < 4; ++k) {
            int i = tid + k * 128;
            int row = i >> 3, c8 = i & 7;
            int gr = node0 + row;
            const __half* src = (gr < N) ? (zr + (size_t)gr * 64) : zr;
            cp16(dst + row * 72 + c8 * 8, src + c8 * 8);
        }
    }
}

__device__ void att_compute(const ATab& a, int tile, const __half* buf, float* wl, int tid) {
    const __half* z[3]; int node0, N, isU;
    att_bases(a, tile, z, node0, N, isU);
    const float* b1 = isU ? a.ub1 : a.ib1;
    const float* w2 = isU ? a.uw2 : a.iw2;
    const float2* wf = a.awf + (isU ? 0 : 1024);
    float* out = isU ? a.out_u : a.out_i;

    const int wid = tid >> 5;
    const int lane = tid & 31;
    const int g = lane >> 2;
    const int t4 = lane & 3;

#pragma unroll
    for (int rel = 0; rel < 3; ++rel) {
        const __half* xr0 = buf + rel * ATT_TILE_H + (wid * 16 + g) * 72;
        const __half* xr1 = xr0 + 8 * 72;
        float acc[4][4];
#pragma unroll
        for (int nt = 0; nt < 4; ++nt)
#pragma unroll
            for (int i = 0; i < 4; ++i) acc[nt][i] = 0.f;
#pragma unroll
        for (int kt = 0; kt < 8; ++kt) {
            int c0 = kt * 8 + t4;
            unsigned int a0 = tf32c(__half2float(xr0[c0]));
            unsigned int a1 = tf32c(__half2float(xr1[c0]));
            unsigned int a2 = tf32c(__half2float(xr0[c0 + 4]));
            unsigned int a3 = tf32c(__half2float(xr1[c0 + 4]));
            const float2* wr = wf + kt * 128 + lane;
#pragma unroll
            for (int nt = 0; nt < 4; ++nt) {
                float2 w = wr[nt * 32];
                mma_tf32(acc[nt], a0, a1, a2, a3,
                         __float_as_uint(w.x), __float_as_uint(w.y));
            }
        }
        float s0 = 0.f, s1 = 0.f;
#pragma unroll
        for (int nt = 0; nt < 4; ++nt) {
            int col = nt * 8 + 2 * t4;
            float b1x = b1[col], b1y = b1[col + 1];
            float w2x = w2[col], w2y = w2[col + 1];
            s0 += tanhf(acc[nt][0] + b1x) * w2x + tanhf(acc[nt][1] + b1y) * w2y;
            s1 += tanhf(acc[nt][2] + b1x) * w2x + tanhf(acc[nt][3] + b1y) * w2y;
        }
        s0 += __shfl_xor_sync(0xffffffffu, s0, 1);
        s0 += __shfl_xor_sync(0xffffffffu, s0, 2);
        s1 += __shfl_xor_sync(0xffffffffu, s1, 1);
        s1 += __shfl_xor_sync(0xffffffffu, s1, 2);
        if (t4 == 0) {
            int r0 = wid * 16 + g;
            wl[r0 * 4 + rel] = s0;
            wl[(r0 + 8) * 4 + rel] = s1;
        }
    }
    __syncthreads();

    {
        int row = tid >> 1;
        int gr = node0 + row;
        if (gr < N) {
            float w0 = wl[row * 4 + 0], w1v = wl[row * 4 + 1], w2v = wl[row * 4 + 2];
            float mx = fmaxf(w0, fmaxf(w1v, w2v));
            float e0 = __expf(w0 - mx), e1 = __expf(w1v - mx), e2 = __expf(w2v - mx);
            float inv = 1.0f / (e0 + e1 + e2);
            float beta0 = e0 * inv, beta1 = e1 * inv, beta2 = e2 * inv;
            int hoff = (tid & 1) * 32;
            const __half2* z0p = reinterpret_cast<const __half2*>(
                buf + 0 * ATT_TILE_H + row * 72 + hoff);
            const __half2* z1p = reinterpret_cast<const __half2*>(
                buf + 1 * ATT_TILE_H + row * 72 + hoff);
            const __half2* z2p = reinterpret_cast<const __half2*>(
                buf + 2 * ATT_TILE_H + row * 72 + hoff);
            float* op = out + (size_t)gr * 64 + hoff;
#pragma unroll
            for (int i = 0; i < 16; ++i) {
                float2 A = __half22float2(z0p[i]);
                float2 B = __half22float2(z1p[i]);
                float2 C = __half22float2(z2p[i]);
                float2 o;
                o.x = beta0 * A.x + beta1 * B.x + beta2 * C.x;
                o.y = beta0 * A.y + beta1 * B.y + beta2 * C.y;
                *reinterpret_cast<float2*>(op + i * 2) = o;
            }
        }
    }
}

__global__ __launch_bounds__(128) void rel_att_tc(ATab a)
{
    extern __shared__ __align__(16) __half smh[];
    __half* buf0 = smh;
    __half* buf1 = smh + ATT_BUF_H;
    float* wl = reinterpret_cast<float*>(smh + 2 * ATT_BUF_H);
    const int tid = threadIdx.x;
    const int stride = gridDim.x;
    int t0 = (int)blockIdx.x;
    if (t0 >= a.total) return;

    att_stage(a, t0, buf0, tid);
    asm volatile("cp.async.commit_group;" ::: "memory");

    int cur = 0;
    for (int t = t0; t < a.total; t += stride) {
        int nxt = t + stride;
        if (nxt < a.total) {
            att_stage(a, nxt, cur ? buf0 : buf1, tid);
            asm volatile("cp.async.commit_group;" ::: "memory");
            asm volatile("cp.async.wait_group 1;" ::: "memory");
        } else {
            asm volatile("cp.async.wait_group 0;" ::: "memory");
        }
        __syncthreads();
        att_compute(a, t, cur ? buf1 : buf0, wl, tid);
        __syncthreads();
        cur ^= 1;
    }
}

// ---------------- host launcher ----------------
extern "C" void kernel_launch(void* const* d_in, const int* in_sizes, int n_in,
                              void* d_out, int out_size)
{
    const int*   u2i_idx  = (const int*)  d_in[0];
    const float* u2i_val  = (const float*)d_in[1];
    const int*   u2e_idx  = (const int*)  d_in[2];
    const float* u2e_val  = (const float*)d_in[3];
    const int*   i2e_idx  = (const int*)  d_in[4];
    const float* i2e_val  = (const float*)d_in[5];
    const float* u_feat   = (const float*)d_in[6];
    const float* i_feat   = (const float*)d_in[7];
    const float* u2e_feat = (const float*)d_in[8];
    const float* i2e_feat = (const float*)d_in[9];
    const float* Tw_u2i = (const float*)d_in[10];
    const float* Tb_u2i = (const float*)d_in[11];
    const float* Iw_u2i = (const float*)d_in[12];
    const float* Ib_u2i = (const float*)d_in[13];
    const float* Tw_u2e = (const float*)d_in[14];
    const float* Tb_u2e = (const float*)d_in[15];
    const float* Iw_u2e = (const float*)d_in[16];
    const float* Ib_u2e = (const float*)d_in[17];
    const float* Tw_i2e = (const float*)d_in[18];
    const float* Tb_i2e = (const float*)d_in[19];
    const float* Iw_i2e = (const float*)d_in[20];
    const float* Ib_i2e = (const float*)d_in[21];
    const float* uatt_w1 = (const float*)d_in[22];
    const float* uatt_b1 = (const float*)d_in[23];
    const float* uatt_w2 = (const float*)d_in[24];
    const float* iatt_w1 = (const float*)d_in[25];
    const float* iatt_b1 = (const float*)d_in[26];
    const float* iatt_w2 = (const float*)d_in[27];

    const int U = in_sizes[6] / 64;
    const int I = in_sizes[7] / 64;
    const int E = in_sizes[8] / (2 * 64);
    const int NNZ_UI = in_sizes[1];
    const int NNZ_E  = in_sizes[3] / 2;

    __half *tu, *ti, *t, *s;
    float2 *wT, *wI, *awf;
    cudaGetSymbolAddress((void**)&tu, g_tu);
    cudaGetSymbolAddress((void**)&ti, g_ti);
    cudaGetSymbolAddress((void**)&t,  g_t);
    cudaGetSymbolAddress((void**)&s,  g_s);
    cudaGetSymbolAddress((void**)&wT, g_wT);
    cudaGetSymbolAddress((void**)&wI, g_wI);
    cudaGetSymbolAddress((void**)&awf, g_awf);

    float* outp    = (float*)d_out;
    float* out_u   = outp;
    float* out_i   = outp + (size_t)U * 64;
    float* out_u2e = outp + (size_t)(U + I) * 64;
    float* out_i2e = out_u2e + (size_t)2 * E * 64;

    int ns[5]  = {U + E, U + E, I + E, I + E, U + I};
    int rb[6];
    rb[0] = 0;
    for (int i = 0; i < 5; ++i) rb[i + 1] = rb[i] + ns[i];

    pack_all<<<48, 256>>>(
        Tw_u2e, Iw_u2e, Tw_u2e + 4096, Iw_u2e + 4096,
        Tw_i2e, Iw_i2e, Tw_i2e + 4096, Iw_i2e + 4096,
        Tw_u2i, Iw_u2i, wT, wI,
        uatt_w1, iatt_w1, awf);

    GTab gt;
    {
        const float* xAs[5] = {u_feat, u_feat, i_feat, i_feat, u_feat};
        const float* xBs[5] = {u2e_feat, u2e_feat + (size_t)E * 64,
                               i2e_feat, i2e_feat + (size_t)E * 64, i_feat};
        int nXs[5] = {U, U, I, I, U};
        int nHs[5] = {U, U, I, I, U + I};
        const float* Tbs[5] = {Tb_u2e, Tb_u2e + 64, Tb_i2e, Tb_i2e + 64, Tb_u2i};
        const float* Ibs[5] = {Ib_u2e, Ib_u2e + 64, Ib_i2e, Ib_i2e + 64, Ib_u2i};
        __half* outAs[5] = {tu, tu + (size_t)U * 64, ti, ti + (size_t)I * 64, t};
        float* outBs[5] = {out_u2e, out_u2e + (size_t)E * 64,
                           out_i2e, out_i2e + (size_t)E * 64, out_u2e};
        gt.off[0] = 0;
        for (int i = 0; i < 5; ++i) {
            gt.c[i].xA = xAs[i]; gt.c[i].xB = xBs[i];
            gt.c[i].nX = nXs[i]; gt.c[i].nH = nHs[i]; gt.c[i].n = ns[i];
            gt.c[i].wT = wT + (size_t)i * 2048;
            gt.c[i].wI = wI + (size_t)i * 2048;
            gt.c[i].Tb = Tbs[i]; gt.c[i].Ib = Ibs[i];
            gt.c[i].outA = outAs[i]; gt.c[i].outB = outBs[i];
            gt.c[i].s = s + (size_t)rb[i] * 64;
            gt.off[i + 1] = gt.off[i] + (ns[i] + 63) / 64;
        }
    }
    int totalTiles = gt.off[5];
    int gemmGrid = 152 * 5;
    if (gemmGrid > totalTiles) gemmGrid = totalTiles;
    gcn_gemm_all<<<gemmGrid, 128>>>(gt, totalTiles);

    STab st;
    {
        const int* rws[5] = {u2e_idx, u2e_idx + (size_t)2 * NNZ_E,
                             i2e_idx, i2e_idx + (size_t)2 * NNZ_E, u2i_idx};
        const float* vls[5] = {u2e_val, u2e_val + NNZ_E,
                               i2e_val, i2e_val + NNZ_E, u2i_val};
        int nnzs[5] = {NNZ_E, NNZ_E, NNZ_E, NNZ_E, NNZ_UI};
        int nHs[5]  = {U, U, I, I, U + I};
        __half* outAs[5] = {tu, tu + (size_t)U * 64, ti, ti + (size_t)I * 64, t};
        float* outBs[5] = {out_u2e, out_u2e + (size_t)E * 64,
                           out_i2e, out_i2e + (size_t)E * 64, out_u2e};
        st.off[0] = 0;
        for (int i = 0; i < 5; ++i) {
            st.c[i].rows = rws[i];
            st.c[i].cols = rws[i] + nnzs[i];
            st.c[i].vals = vls[i];
            st.c[i].nnz = nnzs[i];
            st.c[i].sIn = s + (size_t)rb[i] * 64;
            st.c[i].outA = outAs[i];
            st.c[i].nH = nHs[i];
            st.c[i].outB = outBs[i];
            long long th = ((long long)nnzs[i] + 1) / 2 * 8;   // 8 lanes per edge-pair
            st.off[i + 1] = st.off[i] + (int)((th + 255) / 256);
        }
    }
    spmm_all<<<st.off[5], 256>>>(st);

    ATab at;
    at.tu = tu; at.ti = ti; at.t = t;
    at.U = U; at.I = I;
    at.nbU = (U + 63) / 64;
    at.total = at.nbU + (I + 63) / 64;
    at.awf = awf;
    at.ub1 = uatt_b1; at.uw2 = uatt_w2;
    at.ib1 = iatt_b1; at.iw2 = iatt_w2;
    at.out_u = out_u; at.out_i = out_i;

    cudaFuncSetAttribute(rel_att_tc, cudaFuncAttributeMaxDynamicSharedMemorySize,
                         ATT_SMEM_B);
    int attGrid = 152 * 4;
    if (attGrid > at.total) attGrid = at.total;
    rel_att_tc<<<attGrid, 128, ATT_SMEM_B>>>(at);
}

// round 16
// speedup vs baseline: 1.3139x; 1.1098x over previous
#include <cuda_runtime.h>
#include <cuda_fp16.h>
#include <cstdint>
#include <cstdio>

// ---------------- scratch (static device globals; no allocation) ----------------
__device__ __half g_tu[2 * 100000 * 64];
__device__ __half g_ti[2 * 100000 * 64];
__device__ __half g_t [200000 * 64];
__device__ __half g_s [800000 * 64];
__device__ uint2 g_wT16[5 * 1024];   // fp16 B-frags: [cell][kt4][nt8][lane32]
__device__ uint2 g_wI16[5 * 1024];
__device__ uint2 g_awf16[1024];      // attention w1 frags: [set2][kt4][nt4][lane32]

// ---------------- helpers ----------------
__device__ __forceinline__ void red4(float* p, float a, float b, float c, float d) {
    asm volatile("red.global.add.v4.f32 [%0], {%1, %2, %3, %4};"
                 :: "l"(p), "f"(a), "f"(b), "f"(c), "f"(d) : "memory");
}
__device__ __forceinline__ void redh8(__half* p,
                                      float f0, float f1, float f2, float f3,
                                      float f4, float f5, float f6, float f7) {
    __half2 h0 = __floats2half2_rn(f0, f1);
    __half2 h1 = __floats2half2_rn(f2, f3);
    __half2 h2 = __floats2half2_rn(f4, f5);
    __half2 h3 = __floats2half2_rn(f6, f7);
    unsigned x0 = *reinterpret_cast<unsigned*>(&h0);
    unsigned x1 = *reinterpret_cast<unsigned*>(&h1);
    unsigned x2 = *reinterpret_cast<unsigned*>(&h2);
    unsigned x3 = *reinterpret_cast<unsigned*>(&h3);
    asm volatile("red.global.add.noftz.v4.f16x2 [%0], {%1, %2, %3, %4};"
                 :: "l"(p), "r"(x0), "r"(x1), "r"(x2), "r"(x3) : "memory");
}
// fp16 MMA m16n8k16, fp32 accumulate (acc layout identical to m16n8k8)
__device__ __forceinline__ void mma_f16(float c[4],
                                        unsigned a0, unsigned a1,
                                        unsigned a2, unsigned a3,
                                        unsigned b0, unsigned b1) {
    asm("mma.sync.aligned.m16n8k16.row.col.f32.f16.f16.f32 "
        "{%0,%1,%2,%3}, {%4,%5,%6,%7}, {%8,%9}, {%0,%1,%2,%3};"
        : "+f"(c[0]), "+f"(c[1]), "+f"(c[2]), "+f"(c[3])
        : "r"(a0), "r"(a1), "r"(a2), "r"(a3), "r"(b0), "r"(b1));
}
__device__ __forceinline__ unsigned h2u(__half2 h) {
    return *reinterpret_cast<unsigned*>(&h);
}
__device__ __forceinline__ void cp16(void* dst_smem, const void* src) {
    unsigned d = (unsigned)__cvta_generic_to_shared(dst_smem);
    asm volatile("cp.async.cg.shared.global [%0], [%1], 16;" :: "r"(d), "l"(src));
}

// ---------------- descriptor tables ----------------
struct GCell {
    const float* xA; const float* xB; int nX; int nH; int n;
    const uint2* wT; const uint2* wI;
    const float* Tb; const float* Ib;
    __half* outA; float* outB; __half* s;
};
struct GTab { int off[6]; GCell c[5]; };

struct SCell {
    const int* rows; const int* cols; const float* vals; int nnz;
    const __half* sIn; __half* outA; int nH; float* outB;
};
struct STab { int off[6]; SCell c[5]; };

// ---------------- combined weight fragment packer ----------------
// GEMM frag: b0 = (w[k0][n], w[k0+1][n]); b1 = (w[k0+8][n], w[k0+9][n]);
//            k0 = kt*16 + (l&3)*2, n = nt*8 + (l>>2)
__global__ __launch_bounds__(256) void pack_all(
    const float* tw0, const float* iw0, const float* tw1, const float* iw1,
    const float* tw2, const float* iw2, const float* tw3, const float* iw3,
    const float* tw4, const float* iw4, uint2* wT, uint2* wI,
    const float* uw1, const float* iw1a, uint2* awf)
{
    int idx = blockIdx.x * 256 + threadIdx.x;
    if (idx < 5 * 1024) {
        int c = idx >> 10;
        int r = idx & 1023;
        int kt = (r >> 8) & 3;
        int nt = (r >> 5) & 7;
        int l = r & 31;
        const float* tw; const float* iw;
        switch (c) {
            case 0: tw = tw0; iw = iw0; break;
            case 1: tw = tw1; iw = iw1; break;
            case 2: tw = tw2; iw = iw2; break;
            case 3: tw = tw3; iw = iw3; break;
            default: tw = tw4; iw = iw4; break;
        }
        int k0 = kt * 16 + (l & 3) * 2;
        int n0 = nt * 8 + (l >> 2);
        uint2 ot, oi;
        ot.x = h2u(__floats2half2_rn(tw[k0 * 64 + n0], tw[(k0 + 1) * 64 + n0]));
        ot.y = h2u(__floats2half2_rn(tw[(k0 + 8) * 64 + n0], tw[(k0 + 9) * 64 + n0]));
        oi.x = h2u(__floats2half2_rn(iw[k0 * 64 + n0], iw[(k0 + 1) * 64 + n0]));
        oi.y = h2u(__floats2half2_rn(iw[(k0 + 8) * 64 + n0], iw[(k0 + 9) * 64 + n0]));
        wT[idx] = ot;
        wI[idx] = oi;
    } else if (idx < 5 * 1024 + 1024) {
        int j = idx - 5 * 1024;
        int set = j >> 9;
        int kt = (j >> 7) & 3;
        int nt = (j >> 5) & 3;
        int l = j & 31;
        const float* w = set ? iw1a : uw1;
        int k0 = kt * 16 + (l & 3) * 2;
        int n0 = nt * 8 + (l >> 2);
        uint2 o;
        o.x = h2u(__floats2half2_rn(w[k0 * 32 + n0], w[(k0 + 1) * 32 + n0]));
        o.y = h2u(__floats2half2_rn(w[(k0 + 8) * 32 + n0], w[(k0 + 9) * 32 + n0]));
        awf[j] = o;
    }
}

// ---------------- fused dual GEMM (fp16 MMA k16) ----------------
__device__ __forceinline__ int cell_of(const GTab& tab, int b) {
    int c = 0;
#pragma unroll
    for (int i = 1; i < 5; ++i) c += (b >= tab.off[i]);
    return c;
}

__device__ __forceinline__ void stage_tile(const GTab& tab, int b, float* buf, int tid) {
    int c = cell_of(tab, b);
    const GCell& cl = tab.c[c];
    int row0 = (b - tab.off[c]) * 64;
#pragma unroll
    for (int k = 0; k < 8; ++k) {
        int j = tid + k * 128;
        int r = j >> 4, seg = j & 15;
        int gr = row0 + r;
        const float* src;
        if (gr < cl.n)
            src = (gr < cl.nX) ? (cl.xA + (size_t)gr * 64)
                               : (cl.xB + (size_t)(gr - cl.nX) * 64);
        else
            src = cl.xA;
        cp16(buf + r * 68 + seg * 4, src + seg * 4);
    }
}

__device__ void compute_tile(const GTab& tab, int b, const float* sX, int tid) {
    int c = cell_of(tab, b);
    const GCell cl = tab.c[c];
    const int row0 = (b - tab.off[c]) * 64;
    const int n = cl.n;

    const int wid = tid >> 5;
    const int lane = tid & 31;
    const int g = lane >> 2;
    const int t4 = lane & 3;
    const float* xr0 = sX + (wid * 16 + g) * 68;
    const float* xr1 = xr0 + 8 * 68;

    float acc[8][4];
#pragma unroll
    for (int nt = 0; nt < 8; ++nt)
#pragma unroll
        for (int i = 0; i < 4; ++i) acc[nt][i] = 0.f;

    // T phase: 4 kt-iters of k=16
#pragma unroll
    for (int kt = 0; kt < 4; ++kt) {
        int c0 = kt * 16 + t4 * 2;
        float2 xa = *reinterpret_cast<const float2*>(xr0 + c0);
        float2 xb = *reinterpret_cast<const float2*>(xr1 + c0);
        float2 xc = *reinterpret_cast<const float2*>(xr0 + c0 + 8);
        float2 xd = *reinterpret_cast<const float2*>(xr1 + c0 + 8);
        unsigned a0 = h2u(__floats2half2_rn(xa.x, xa.y));
        unsigned a1 = h2u(__floats2half2_rn(xb.x, xb.y));
        unsigned a2 = h2u(__floats2half2_rn(xc.x, xc.y));
        unsigned a3 = h2u(__floats2half2_rn(xd.x, xd.y));
        const uint2* wr = cl.wT + kt * 256 + lane;
#pragma unroll
        for (int nt = 0; nt < 8; ++nt) {
            uint2 w = wr[nt * 32];
            mma_f16(acc[nt], a0, a1, a2, a3, w.x, w.y);
        }
    }

    const int r0 = row0 + wid * 16 + g;
    const int r1 = r0 + 8;

#pragma unroll
    for (int nt = 0; nt < 8; ++nt) {
        int col = nt * 8 + 2 * t4;
        float tbx = cl.Tb[col], tby = cl.Tb[col + 1];
        if (r0 < n) {
            float tv0 = acc[nt][0] + tbx, tv1 = acc[nt][1] + tby;
            if (r0 < cl.nH)
                *reinterpret_cast<__half2*>(cl.outA + (size_t)r0 * 64 + col) =
                    __floats2half2_rn(tv0, tv1);
            else
                *reinterpret_cast<float2*>(cl.outB + (size_t)(r0 - cl.nH) * 64 + col) =
                    make_float2(tv0, tv1);
        }
        if (r1 < n) {
            float tv0 = acc[nt][2] + tbx, tv1 = acc[nt][3] + tby;
            if (r1 < cl.nH)
                *reinterpret_cast<__half2*>(cl.outA + (size_t)r1 * 64 + col) =
                    __floats2half2_rn(tv0, tv1);
            else
                *reinterpret_cast<float2*>(cl.outB + (size_t)(r1 - cl.nH) * 64 + col) =
                    make_float2(tv0, tv1);
        }
    }

    // Q phase
#pragma unroll
    for (int kt = 0; kt < 4; ++kt) {
        int c0 = kt * 16 + t4 * 2;
        float2 xa = *reinterpret_cast<const float2*>(xr0 + c0);
        float2 xb = *reinterpret_cast<const float2*>(xr1 + c0);
        float2 xc = *reinterpret_cast<const float2*>(xr0 + c0 + 8);
        float2 xd = *reinterpret_cast<const float2*>(xr1 + c0 + 8);
        unsigned a0 = h2u(__floats2half2_rn(xa.x * xa.x, xa.y * xa.y));
        unsigned a1 = h2u(__floats2half2_rn(xb.x * xb.x, xb.y * xb.y));
        unsigned a2 = h2u(__floats2half2_rn(xc.x * xc.x, xc.y * xc.y));
        unsigned a3 = h2u(__floats2half2_rn(xd.x * xd.x, xd.y * xd.y));
        const uint2* wr = cl.wI + kt * 256 + lane;
#pragma unroll
        for (int nt = 0; nt < 8; ++nt) {
            uint2 w = wr[nt * 32];
            mma_f16(acc[nt], a0, a1, a2, a3, w.x, w.y);
        }
    }

#pragma unroll
    for (int nt = 0; nt < 8; ++nt) {
        int col = nt * 8 + 2 * t4;
        float sbx = cl.Tb[col] + cl.Ib[col];
        float sby = cl.Tb[col + 1] + cl.Ib[col + 1];
        if (r0 < n)
            *reinterpret_cast<__half2*>(cl.s + (size_t)r0 * 64 + col) =
                __floats2half2_rn(acc[nt][0] + sbx, acc[nt][1] + sby);
        if (r1 < n)
            *reinterpret_cast<__half2*>(cl.s + (size_t)r1 * 64 + col) =
                __floats2half2_rn(acc[nt][2] + sbx, acc[nt][3] + sby);
    }
}

__global__ __launch_bounds__(128, 5) void gcn_gemm_all(GTab tab, int total)
{
    __shared__ __align__(16) float sbuf[2][64 * 68];
    const int tid = threadIdx.x;
    const int stride = gridDim.x;
    int t0 = (int)blockIdx.x;
    if (t0 >= total) return;

    stage_tile(tab, t0, sbuf[0], tid);
    asm volatile("cp.async.commit_group;" ::: "memory");

    int cur = 0;
    for (int t = t0; t < total; t += stride) {
        int nxt = t + stride;
        if (nxt < total) {
            stage_tile(tab, nxt, sbuf[1 - cur], tid);
            asm volatile("cp.async.commit_group;" ::: "memory");
            asm volatile("cp.async.wait_group 1;" ::: "memory");
        } else {
            asm volatile("cp.async.wait_group 0;" ::: "memory");
        }
        __syncthreads();
        compute_tile(tab, t, sbuf[cur], tid);
        __syncthreads();
        cur ^= 1;
    }
}

// ---------------- fused edge scatter: 8 lanes/edge, 16B gathers + 16B reds ----------------
__global__ __launch_bounds__(256) void spmm_all(STab tab)
{
    int b = blockIdx.x;
    int c = 0;
#pragma unroll
    for (int i = 1; i < 5; ++i) c += (b >= tab.off[i]);
    const SCell cl = tab.c[c];
    long long t = (long long)(b - tab.off[c]) * 256 + threadIdx.x;
    int l = (int)(t & 7);
    int e0 = (int)(t >> 3) * 2;
    if (e0 >= cl.nnz) return;

    int r0 = __ldg(cl.rows + e0);
    int c0 = __ldg(cl.cols + e0);
    float v0 = __ldg(cl.vals + e0);
    bool has1 = (e0 + 1) < cl.nnz;
    int r1 = r0, c1 = c0;
    float v1 = 0.f;
    if (has1) {
        r1 = __ldg(cl.rows + e0 + 1);
        c1 = __ldg(cl.cols + e0 + 1);
        v1 = __ldg(cl.vals + e0 + 1);
    }
    uint4 u0 = *reinterpret_cast<const uint4*>(cl.sIn + (size_t)c0 * 64 + l * 8);
    uint4 u1 = *reinterpret_cast<const uint4*>(cl.sIn + (size_t)c1 * 64 + l * 8);

    {
        float2 p0 = __half22float2(*reinterpret_cast<__half2*>(&u0.x));
        float2 p1 = __half22float2(*reinterpret_cast<__half2*>(&u0.y));
        float2 p2 = __half22float2(*reinterpret_cast<__half2*>(&u0.z));
        float2 p3 = __half22float2(*reinterpret_cast<__half2*>(&u0.w));
        if (r0 < cl.nH) {
            redh8(cl.outA + (size_t)r0 * 64 + l * 8,
                  v0 * p0.x, v0 * p0.y, v0 * p1.x, v0 * p1.y,
                  v0 * p2.x, v0 * p2.y, v0 * p3.x, v0 * p3.y);
        } else {
            float* p = cl.outB + (size_t)(r0 - cl.nH) * 64 + l * 8;
            red4(p,     v0 * p0.x, v0 * p0.y, v0 * p1.x, v0 * p1.y);
            red4(p + 4, v0 * p2.x, v0 * p2.y, v0 * p3.x, v0 * p3.y);
        }
    }
    if (has1) {
        float2 p0 = __half22float2(*reinterpret_cast<__half2*>(&u1.x));
        float2 p1 = __half22float2(*reinterpret_cast<__half2*>(&u1.y));
        float2 p2 = __half22float2(*reinterpret_cast<__half2*>(&u1.z));
        float2 p3 = __half22float2(*reinterpret_cast<__half2*>(&u1.w));
        if (r1 < cl.nH) {
            redh8(cl.outA + (size_t)r1 * 64 + l * 8,
                  v1 * p0.x, v1 * p0.y, v1 * p1.x, v1 * p1.y,
                  v1 * p2.x, v1 * p2.y, v1 * p3.x, v1 * p3.y);
        } else {
            float* p = cl.outB + (size_t)(r1 - cl.nH) * 64 + l * 8;
            red4(p,     v1 * p0.x, v1 * p0.y, v1 * p1.x, v1 * p1.y);
            red4(p + 4, v1 * p2.x, v1 * p2.y, v1 * p3.x, v1 * p3.y);
        }
    }
}

// ---------------- persistent tensor-core attention (fp16 z, fp16 MMA) ----------------
#define ATT_TILE_H (64 * 72)
#define ATT_BUF_H  (3 * ATT_TILE_H)
#define ATT_SMEM_B (2 * ATT_BUF_H * 2 + 64 * 4 * 4 + 64)

struct ATab {
    const __half* tu; const __half* ti; const __half* t;
    int U, I, nbU, total;
    const uint2* awf;
    const float* ub1; const float* uw2;
    const float* ib1; const float* iw2;
    float* out_u; float* out_i;
};

__device__ __forceinline__ void att_bases(const ATab& a, int tile,
                                          const __half** z, int& node0, int& N,
                                          int& isU) {
    isU = (tile < a.nbU);
    node0 = (isU ? tile : (tile - a.nbU)) * 64;
    if (isU) {
        N = a.U; z[0] = a.tu; z[1] = a.tu + (size_t)a.U * 64; z[2] = a.t;
    } else {
        N = a.I; z[0] = a.ti; z[1] = a.ti + (size_t)a.I * 64;
        z[2] = a.t + (size_t)a.U * 64;
    }
}

__device__ __forceinline__ void att_stage(const ATab& a, int tile, __half* buf, int tid) {
    const __half* z[3]; int node0, N, isU;
    att_bases(a, tile, z, node0, N, isU);
#pragma unroll
    for (int r = 0; r < 3; ++r) {
        const __half* zr = z[r];
        __half* dst = buf + r * ATT_TILE_H;
#pragma unroll
        for (int k = 0; k < 4; ++k) {
            int i = tid + k * 128;
            int row = i >> 3, c8 = i & 7;
            int gr = node0 + row;
            const __half* src = (gr < N) ? (zr + (size_t)gr * 64) : zr;
            cp16(dst + row * 72 + c8 * 8, src + c8 * 8);
        }
    }
}

__device__ void att_compute(const ATab& a, int tile, const __half* buf, float* wl, int tid) {
    const __half* z[3]; int node0, N, isU;
    att_bases(a, tile, z, node0, N, isU);
    const float* b1 = isU ? a.ub1 : a.ib1;
    const float* w2 = isU ? a.uw2 : a.iw2;
    const uint2* wf = a.awf + (isU ? 0 : 512);
    float* out = isU ? a.out_u : a.out_i;

    const int wid = tid >> 5;
    const int lane = tid & 31;
    const int g = lane >> 2;
    const int t4 = lane & 3;

#pragma unroll
    for (int rel = 0; rel < 3; ++rel) {
        const __half* xr0 = buf + rel * ATT_TILE_H + (wid * 16 + g) * 72;
        const __half* xr1 = xr0 + 8 * 72;
        float acc[4][4];
#pragma unroll
        for (int nt = 0; nt < 4; ++nt)
#pragma unroll
            for (int i = 0; i < 4; ++i) acc[nt][i] = 0.f;
#pragma unroll
        for (int kt = 0; kt < 4; ++kt) {
            int c0 = kt * 16 + t4 * 2;
            unsigned a0 = *reinterpret_cast<const unsigned*>(xr0 + c0);
            unsigned a1 = *reinterpret_cast<const unsigned*>(xr1 + c0);
            unsigned a2 = *reinterpret_cast<const unsigned*>(xr0 + c0 + 8);
            unsigned a3 = *reinterpret_cast<const unsigned*>(xr1 + c0 + 8);
            const uint2* wr = wf + kt * 128 + lane;
#pragma unroll
            for (int nt = 0; nt < 4; ++nt) {
                uint2 w = wr[nt * 32];
                mma_f16(acc[nt], a0, a1, a2, a3, w.x, w.y);
            }
        }
        float s0 = 0.f, s1 = 0.f;
#pragma unroll
        for (int nt = 0; nt < 4; ++nt) {
            int col = nt * 8 + 2 * t4;
            float b1x = b1[col], b1y = b1[col + 1];
            float w2x = w2[col], w2y = w2[col + 1];
            s0 += tanhf(acc[nt][0] + b1x) * w2x + tanhf(acc[nt][1] + b1y) * w2y;
            s1 += tanhf(acc[nt][2] + b1x) * w2x + tanhf(acc[nt][3] + b1y) * w2y;
        }
        s0 += __shfl_xor_sync(0xffffffffu, s0, 1);
        s0 += __shfl_xor_sync(0xffffffffu, s0, 2);
        s1 += __shfl_xor_sync(0xffffffffu, s1, 1);
        s1 += __shfl_xor_sync(0xffffffffu, s1, 2);
        if (t4 == 0) {
            int r0 = wid * 16 + g;
            wl[r0 * 4 + rel] = s0;
            wl[(r0 + 8) * 4 + rel] = s1;
        }
    }
    __syncthreads();

    {
        int row = tid >> 1;
        int gr = node0 + row;
        if (gr < N) {
            float w0 = wl[row * 4 + 0], w1v = wl[row * 4 + 1], w2v = wl[row * 4 + 2];
            float mx = fmaxf(w0, fmaxf(w1v, w2v));
            float e0 = __expf(w0 - mx), e1 = __expf(w1v - mx), e2 = __expf(w2v - mx);
            float inv = 1.0f / (e0 + e1 + e2);
            float beta0 = e0 * inv, beta1 = e1 * inv, beta2 = e2 * inv;
            int hoff = (tid & 1) * 32;
            const __half2* z0p = reinterpret_cast<const __half2*>(
                buf + 0 * ATT_TILE_H + row * 72 + hoff);
            const __half2* z1p = reinterpret_cast<const __half2*>(
                buf + 1 * ATT_TILE_H + row * 72 + hoff);
            const __half2* z2p = reinterpret_cast<const __half2*>(
                buf + 2 * ATT_TILE_H + row * 72 + hoff);
            float* op = out + (size_t)gr * 64 + hoff;
#pragma unroll
            for (int i = 0; i < 16; ++i) {
                float2 A = __half22float2(z0p[i]);
                float2 B = __half22float2(z1p[i]);
                float2 C = __half22float2(z2p[i]);
                float2 o;
                o.x = beta0 * A.x + beta1 * B.x + beta2 * C.x;
                o.y = beta0 * A.y + beta1 * B.y + beta2 * C.y;
                *reinterpret_cast<float2*>(op + i * 2) = o;
            }
        }
    }
}

__global__ __launch_bounds__(128) void rel_att_tc(ATab a)
{
    extern __shared__ __align__(16) __half smh[];
    __half* buf0 = smh;
    __half* buf1 = smh + ATT_BUF_H;
    float* wl = reinterpret_cast<float*>(smh + 2 * ATT_BUF_H);
    const int tid = threadIdx.x;
    const int stride = gridDim.x;
    int t0 = (int)blockIdx.x;
    if (t0 >= a.total) return;

    att_stage(a, t0, buf0, tid);
    asm volatile("cp.async.commit_group;" ::: "memory");

    int cur = 0;
    for (int t = t0; t < a.total; t += stride) {
        int nxt = t + stride;
        if (nxt < a.total) {
            att_stage(a, nxt, cur ? buf0 : buf1, tid);
            asm volatile("cp.async.commit_group;" ::: "memory");
            asm volatile("cp.async.wait_group 1;" ::: "memory");
        } else {
            asm volatile("cp.async.wait_group 0;" ::: "memory");
        }
        __syncthreads();
        att_compute(a, t, cur ? buf1 : buf0, wl, tid);
        __syncthreads();
        cur ^= 1;
    }
}

// ---------------- host launcher ----------------
extern "C" void kernel_launch(void* const* d_in, const int* in_sizes, int n_in,
                              void* d_out, int out_size)
{
    const int*   u2i_idx  = (const int*)  d_in[0];
    const float* u2i_val  = (const float*)d_in[1];
    const int*   u2e_idx  = (const int*)  d_in[2];
    const float* u2e_val  = (const float*)d_in[3];
    const int*   i2e_idx  = (const int*)  d_in[4];
    const float* i2e_val  = (const float*)d_in[5];
    const float* u_feat   = (const float*)d_in[6];
    const float* i_feat   = (const float*)d_in[7];
    const float* u2e_feat = (const float*)d_in[8];
    const float* i2e_feat = (const float*)d_in[9];
    const float* Tw_u2i = (const float*)d_in[10];
    const float* Tb_u2i = (const float*)d_in[11];
    const float* Iw_u2i = (const float*)d_in[12];
    const float* Ib_u2i = (const float*)d_in[13];
    const float* Tw_u2e = (const float*)d_in[14];
    const float* Tb_u2e = (const float*)d_in[15];
    const float* Iw_u2e = (const float*)d_in[16];
    const float* Ib_u2e = (const float*)d_in[17];
    const float* Tw_i2e = (const float*)d_in[18];
    const float* Tb_i2e = (const float*)d_in[19];
    const float* Iw_i2e = (const float*)d_in[20];
    const float* Ib_i2e = (const float*)d_in[21];
    const float* uatt_w1 = (const float*)d_in[22];
    const float* uatt_b1 = (const float*)d_in[23];
    const float* uatt_w2 = (const float*)d_in[24];
    const float* iatt_w1 = (const float*)d_in[25];
    const float* iatt_b1 = (const float*)d_in[26];
    const float* iatt_w2 = (const float*)d_in[27];

    const int U = in_sizes[6] / 64;
    const int I = in_sizes[7] / 64;
    const int E = in_sizes[8] / (2 * 64);
    const int NNZ_UI = in_sizes[1];
    const int NNZ_E  = in_sizes[3] / 2;

    __half *tu, *ti, *t, *s;
    uint2 *wT, *wI, *awf;
    cudaGetSymbolAddress((void**)&tu, g_tu);
    cudaGetSymbolAddress((void**)&ti, g_ti);
    cudaGetSymbolAddress((void**)&t,  g_t);
    cudaGetSymbolAddress((void**)&s,  g_s);
    cudaGetSymbolAddress((void**)&wT, g_wT16);
    cudaGetSymbolAddress((void**)&wI, g_wI16);
    cudaGetSymbolAddress((void**)&awf, g_awf16);

    float* outp    = (float*)d_out;
    float* out_u   = outp;
    float* out_i   = outp + (size_t)U * 64;
    float* out_u2e = outp + (size_t)(U + I) * 64;
    float* out_i2e = out_u2e + (size_t)2 * E * 64;

    int ns[5]  = {U + E, U + E, I + E, I + E, U + I};
    int rb[6];
    rb[0] = 0;
    for (int i = 0; i < 5; ++i) rb[i + 1] = rb[i] + ns[i];

    pack_all<<<24, 256>>>(
        Tw_u2e, Iw_u2e, Tw_u2e + 4096, Iw_u2e + 4096,
        Tw_i2e, Iw_i2e, Tw_i2e + 4096, Iw_i2e + 4096,
        Tw_u2i, Iw_u2i, wT, wI,
        uatt_w1, iatt_w1, awf);

    GTab gt;
    {
        const float* xAs[5] = {u_feat, u_feat, i_feat, i_feat, u_feat};
        const float* xBs[5] = {u2e_feat, u2e_feat + (size_t)E * 64,
                               i2e_feat, i2e_feat + (size_t)E * 64, i_feat};
        int nXs[5] = {U, U, I, I, U};
        int nHs[5] = {U, U, I, I, U + I};
        const float* Tbs[5] = {Tb_u2e, Tb_u2e + 64, Tb_i2e, Tb_i2e + 64, Tb_u2i};
        const float* Ibs[5] = {Ib_u2e, Ib_u2e + 64, Ib_i2e, Ib_i2e + 64, Ib_u2i};
        __half* outAs[5] = {tu, tu + (size_t)U * 64, ti, ti + (size_t)I * 64, t};
        float* outBs[5] = {out_u2e, out_u2e + (size_t)E * 64,
                           out_i2e, out_i2e + (size_t)E * 64, out_u2e};
        gt.off[0] = 0;
        for (int i = 0; i < 5; ++i) {
            gt.c[i].xA = xAs[i]; gt.c[i].xB = xBs[i];
            gt.c[i].nX = nXs[i]; gt.c[i].nH = nHs[i]; gt.c[i].n = ns[i];
            gt.c[i].wT = wT + (size_t)i * 1024;
            gt.c[i].wI = wI + (size_t)i * 1024;
            gt.c[i].Tb = Tbs[i]; gt.c[i].Ib = Ibs[i];
            gt.c[i].outA = outAs[i]; gt.c[i].outB = outBs[i];
            gt.c[i].s = s + (size_t)rb[i] * 64;
            gt.off[i + 1] = gt.off[i] + (ns[i] + 63) / 64;
        }
    }
    int totalTiles = gt.off[5];
    int gemmGrid = 152 * 5;
    if (gemmGrid > totalTiles) gemmGrid = totalTiles;
    gcn_gemm_all<<<gemmGrid, 128>>>(gt, totalTiles);

    STab st;
    {
        const int* rws[5] = {u2e_idx, u2e_idx + (size_t)2 * NNZ_E,
                             i2e_idx, i2e_idx + (size_t)2 * NNZ_E, u2i_idx};
        const float* vls[5] = {u2e_val, u2e_val + NNZ_E,
                               i2e_val, i2e_val + NNZ_E, u2i_val};
        int nnzs[5] = {NNZ_E, NNZ_E, NNZ_E, NNZ_E, NNZ_UI};
        int nHs[5]  = {U, U, I, I, U + I};
        __half* outAs[5] = {tu, tu + (size_t)U * 64, ti, ti + (size_t)I * 64, t};
        float* outBs[5] = {out_u2e, out_u2e + (size_t)E * 64,
                           out_i2e, out_i2e + (size_t)E * 64, out_u2e};
        st.off[0] = 0;
        for (int i = 0; i < 5; ++i) {
            st.c[i].rows = rws[i];
            st.c[i].cols = rws[i] + nnzs[i];
            st.c[i].vals = vls[i];
            st.c[i].nnz = nnzs[i];
            st.c[i].sIn = s + (size_t)rb[i] * 64;
            st.c[i].outA = outAs[i];
            st.c[i].nH = nHs[i];
            st.c[i].outB = outBs[i];
            long long th = ((long long)nnzs[i] + 1) / 2 * 8;
            st.off[i + 1] = st.off[i] + (int)((th + 255) / 256);
        }
    }
    spmm_all<<<st.off[5], 256>>>(st);

    ATab at;
    at.tu = tu; at.ti = ti; at.t = t;
    at.U = U; at.I = I;
    at.nbU = (U + 63) / 64;
    at.total = at.nbU + (I + 63) / 64;
    at.awf = awf;
    at.ub1 = uatt_b1; at.uw2 = uatt_w2;
    at.ib1 = iatt_b1; at.iw2 = iatt_w2;
    at.out_u = out_u; at.out_i = out_i;

    cudaFuncSetAttribute(rel_att_tc, cudaFuncAttributeMaxDynamicSharedMemorySize,
                         ATT_SMEM_B);
    int attGrid = 152 * 4;
    if (attGrid > at.total) attGrid = at.total;
    rel_att_tc<<<attGrid, 128, ATT_SMEM_B>>>(at);
}